// round 8
// baseline (speedup 1.0000x reference)
#include <cuda_runtime.h>
#include <cuda_bf16.h>
#include <math.h>
#include <stdint.h>

// ---------------- problem constants ----------------
#define ROWS 4096        // B*N
#define CDIM 512
#define QKVD 1536
#define HID  2048
#define NHEAD 8
#define HD   64
#define NQ   1024
#define BHN  32768       // B*H*N
#define NBKT 81

// ---------------- device scratch ----------------
__device__ float g_ln    [2][ROWS*CDIM];
__device__ float g_qkv   [2][ROWS*QKVD];
__device__ float g_att   [2][ROWS*CDIM];
__device__ float g_lk    [2][(size_t)BHN*NBKT];
__device__ float g_lq    [2][(size_t)BHN*NBKT];
__device__ float g_hid   [2][(size_t)ROWS*HID];

__constant__ signed char c_pidx[63] = {
  -4,-4,-4,-4,-4,-4,-4,-4,-4,-4,-4,-4,-4,-4,-4,-4,-4,-4,-4,-4,-4,
  -3,-3,-3,-3,-3,-3,-3,
  -2,-2,
  -1,
   0,
   1,
   2, 2,
   3, 3, 3, 3, 3, 3, 3,
   4, 4, 4, 4, 4, 4, 4, 4, 4, 4, 4, 4, 4, 4, 4, 4, 4, 4, 4, 4, 4
};

__device__ __forceinline__ float fexp(float x){
  float y = x * 1.4426950408889634f;
  float n = rintf(y);
  float f = y - n;
  float p =           1.3333558e-3f;
  p = fmaf(p, f, 9.6181291e-3f);
  p = fmaf(p, f, 5.5504108e-2f);
  p = fmaf(p, f, 2.4022650e-1f);
  p = fmaf(p, f, 6.9314718e-1f);
  p = fmaf(p, f, 1.0f);
  int ni = (int)n;
  return p * __int_as_float((ni + 127) << 23);
}

__device__ __forceinline__ uint32_t f2tf32(float v){
  uint32_t r;
  asm("cvt.rna.tf32.f32 %0, %1;" : "=r"(r) : "f"(v));
  return r;
}

__device__ __forceinline__ void mma_tf32(float* c, const uint32_t* a, const uint32_t* b){
  asm volatile(
    "mma.sync.aligned.m16n8k8.row.col.f32.tf32.tf32.f32 "
    "{%0,%1,%2,%3}, {%4,%5,%6,%7}, {%8,%9}, {%0,%1,%2,%3};"
    : "+f"(c[0]), "+f"(c[1]), "+f"(c[2]), "+f"(c[3])
    : "r"(a[0]), "r"(a[1]), "r"(a[2]), "r"(a[3]), "r"(b[0]), "r"(b[1]));
}

// ---------------- layernorm ------------------------------------------------
__global__ void ln_kernel(const float* __restrict__ x, const float* __restrict__ gam,
                          const float* __restrict__ bet, float* __restrict__ y)
{
  int row = blockIdx.x;
  int t = threadIdx.x;
  const float* xr = x + (size_t)row * CDIM;
  float4 v = *(const float4*)(xr + t*4);
  float s  = v.x + v.y + v.z + v.w;
  float s2 = v.x*v.x + v.y*v.y + v.z*v.z + v.w*v.w;
  #pragma unroll
  for (int o = 16; o > 0; o >>= 1){
    s  += __shfl_xor_sync(0xffffffffu, s , o);
    s2 += __shfl_xor_sync(0xffffffffu, s2, o);
  }
  __shared__ float rs[4], rq[4];
  if ((t & 31) == 0){ rs[t>>5] = s; rq[t>>5] = s2; }
  __syncthreads();
  s  = rs[0]+rs[1]+rs[2]+rs[3];
  s2 = rq[0]+rq[1]+rq[2]+rq[3];
  float mu   = s  * (1.0f/CDIM);
  float var  = s2 * (1.0f/CDIM) - mu*mu;
  float rstd = rsqrtf(var + 1e-5f);
  float4 g4 = *(const float4*)(gam + t*4);
  float4 b4 = *(const float4*)(bet + t*4);
  float4 o4;
  o4.x = (v.x-mu)*rstd*g4.x + b4.x;
  o4.y = (v.y-mu)*rstd*g4.y + b4.y;
  o4.z = (v.z-mu)*rstd*g4.z + b4.z;
  o4.w = (v.w-mu)*rstd*g4.w + b4.w;
  *(float4*)(y + (size_t)row*CDIM + t*4) = o4;
}

// ---------------- tf32 tensor-core GEMM ------------------------------------
__global__ void __launch_bounds__(256, 2) sgemm_tf32_kernel(
    const float* __restrict__ A, const float* __restrict__ Bm,
    const float* __restrict__ bias, const float* __restrict__ resid,
    float* __restrict__ C, int M, int N, int K, int gelu)
{
  __shared__ float As[16][132];
  __shared__ float Bs[16][132];
  int t = threadIdx.x;
  int bn = blockIdx.x * 128;
  int bm = blockIdx.y * 128;
  int warp = t >> 5, lane = t & 31;
  int wm = (warp >> 2) << 6;
  int wn = (warp & 3) << 5;
  int g  = lane >> 2;
  int tg = lane & 3;

  float acc[4][4][4];
  #pragma unroll
  for (int mt=0;mt<4;mt++)
    #pragma unroll
    for (int nt=0;nt<4;nt++)
      #pragma unroll
      for (int c=0;c<4;c++) acc[mt][nt][c] = 0.f;

  const float* Ag = A + (size_t)bm * K;
  const float* Bg = Bm + bn;

  for (int k0 = 0; k0 < K; k0 += 16){
    #pragma unroll
    for (int i = 0; i < 2; i++){
      int f = (t<<1) + i;
      int r = f >> 2, kc = (f & 3) << 2;
      float4 v = *(const float4*)(Ag + (size_t)r*K + k0 + kc);
      As[kc+0][r] = __uint_as_float(f2tf32(v.x));
      As[kc+1][r] = __uint_as_float(f2tf32(v.y));
      As[kc+2][r] = __uint_as_float(f2tf32(v.z));
      As[kc+3][r] = __uint_as_float(f2tf32(v.w));
      int kr = f >> 5, nc = (f & 31) << 2;
      float4 w = *(const float4*)(Bg + (size_t)(k0+kr)*N + nc);
      float4 wt;
      wt.x = __uint_as_float(f2tf32(w.x));
      wt.y = __uint_as_float(f2tf32(w.y));
      wt.z = __uint_as_float(f2tf32(w.z));
      wt.w = __uint_as_float(f2tf32(w.w));
      *(float4*)&Bs[kr][nc] = wt;
    }
    __syncthreads();

    #pragma unroll
    for (int ks = 0; ks < 16; ks += 8){
      uint32_t af[4][4], bf[4][2];
      #pragma unroll
      for (int mt = 0; mt < 4; mt++){
        int m = wm + (mt<<4) + g;
        af[mt][0] = __float_as_uint(As[ks+tg  ][m]);
        af[mt][1] = __float_as_uint(As[ks+tg  ][m+8]);
        af[mt][2] = __float_as_uint(As[ks+tg+4][m]);
        af[mt][3] = __float_as_uint(As[ks+tg+4][m+8]);
      }
      #pragma unroll
      for (int nt = 0; nt < 4; nt++){
        int n = wn + (nt<<3) + g;
        bf[nt][0] = __float_as_uint(Bs[ks+tg  ][n]);
        bf[nt][1] = __float_as_uint(Bs[ks+tg+4][n]);
      }
      #pragma unroll
      for (int mt = 0; mt < 4; mt++)
        #pragma unroll
        for (int nt = 0; nt < 4; nt++)
          mma_tf32(acc[mt][nt], af[mt], bf[nt]);
    }
    __syncthreads();
  }

  #pragma unroll
  for (int mt = 0; mt < 4; mt++){
    int row0 = bm + wm + (mt<<4) + g;
    #pragma unroll
    for (int nt = 0; nt < 4; nt++){
      int col = bn + wn + (nt<<3) + (tg<<1);
      float b0 = bias[col], b1 = bias[col+1];
      #pragma unroll
      for (int h = 0; h < 2; h++){
        int row = row0 + (h<<3);
        float r0 = acc[mt][nt][h*2+0] + b0;
        float r1 = acc[mt][nt][h*2+1] + b1;
        if (gelu){
          r0 = 0.5f*r0*(1.0f + erff(r0*0.70710678f));
          r1 = 0.5f*r1*(1.0f + erff(r1*0.70710678f));
        }
        if (resid){
          const float2 rr = *(const float2*)(resid + (size_t)row*N + col);
          r0 += rr.x; r1 += rr.y;
        }
        *(float2*)(C + (size_t)row*N + col) = make_float2(r0, r1);
      }
    }
  }
}

// ---------------- bias tables as tiled GEMM ---------------------------------
__global__ void __launch_bounds__(256) biastab_kernel(
    const float* __restrict__ qkv0, const float* __restrict__ qkv1,
    const float* __restrict__ tq, const float* __restrict__ tk,
    float* __restrict__ lk0, float* __restrict__ lk1,
    float* __restrict__ lq0, float* __restrict__ lq1)
{
  __shared__ float qs[64*65];
  __shared__ float tabT[64*84];

  int t = threadIdx.x;
  int s = blockIdx.z, which = blockIdx.y;
  int base = blockIdx.x << 6;
  const float* src;
  float scl;
  if (which == 0){ src = (s == 0 ? qkv0 : qkv1);       scl = 1.0f;   }
  else           { src = (s == 0 ? qkv1 : qkv0) + 512; scl = 0.125f; }
  const float* tab = (which == 0) ? tk : tq;

  for (int idx = t; idx < NBKT*64; idx += 256){
    int c = idx >> 6, d = idx & 63;
    tabT[d*84 + c] = tab[idx];
  }
  #pragma unroll
  for (int it = 0; it < 4; it++){
    int f = t + (it<<8);
    int r = f >> 4, c4 = (f & 15) << 2;
    int rid = base + r;
    int bh = rid >> 10, n = rid & 1023;
    int b = bh >> 3, h = bh & 7;
    float4 v = *(const float4*)(src + (size_t)((b<<10)+n)*QKVD + (h<<6) + c4);
    qs[r*65+c4+0] = scl*v.x; qs[r*65+c4+1] = scl*v.y;
    qs[r*65+c4+2] = scl*v.z; qs[r*65+c4+3] = scl*v.w;
  }
  __syncthreads();

  int tx = t & 31, ty = t >> 5;
  float acc[8][3];
  #pragma unroll
  for (int i=0;i<8;i++){ acc[i][0]=0.f; acc[i][1]=0.f; acc[i][2]=0.f; }

  #pragma unroll 8
  for (int k = 0; k < 64; k++){
    float b0 = tabT[k*84 + tx];
    float b1 = tabT[k*84 + tx + 32];
    float b2 = (tx < 17) ? tabT[k*84 + tx + 64] : 0.f;
    #pragma unroll
    for (int i = 0; i < 8; i++){
      float a = qs[((ty<<3)+i)*65 + k];
      acc[i][0] = fmaf(a, b0, acc[i][0]);
      acc[i][1] = fmaf(a, b1, acc[i][1]);
      acc[i][2] = fmaf(a, b2, acc[i][2]);
    }
  }

  float* dstbase = (which == 0) ? (s == 0 ? lk0 : lk1) : (s == 0 ? lq0 : lq1);
  #pragma unroll
  for (int i = 0; i < 8; i++){
    int rid = base + (ty<<3) + i;
    float* dst = dstbase + (size_t)rid*NBKT;
    dst[tx]      = acc[i][0];
    dst[tx + 32] = acc[i][1];
    if (tx < 17) dst[tx + 64] = acc[i][2];
  }
}

// ---------------- fused attention: QK^T + bias + online softmax + PV + tv --
// grid (16 i-tiles, 32 bh, 2 streams), 256 threads
// smem floats: qs[4160] ks[4160] vs[4160] ps[4160] lks[5184] lqs[5184]
//              sb[5632] tvs[5984] mrow[64] scl[64] rsv[64]
#define SM_QS   0
#define SM_KS   4160
#define SM_VS   8320
#define SM_PS   12480
#define SM_LKS  16640
#define SM_LQS  21824
#define SM_SB   27008
#define SM_TVS  32640
#define SM_MROW 38624
#define SM_SCL  38688
#define SM_RSV  38752
#define FUSED_SMEM_FLOATS 38816

__global__ void __launch_bounds__(256) fused_attn_kernel(
    const float* __restrict__ qkv0, const float* __restrict__ qkv1,
    const float* __restrict__ lk0, const float* __restrict__ lk1,
    const float* __restrict__ lq0, const float* __restrict__ lq1,
    const float* __restrict__ tv,
    float* __restrict__ att0, float* __restrict__ att1)
{
  extern __shared__ float sm[];
  float* qs  = sm + SM_QS;
  float* ks  = sm + SM_KS;
  float* vs  = sm + SM_VS;
  float* ps  = sm + SM_PS;
  float* lks = sm + SM_LKS;
  float* lqs = sm + SM_LQS;
  float* sb  = sm + SM_SB;
  float* tvs = sm + SM_TVS;
  float* mrow= sm + SM_MROW;
  float* scl = sm + SM_SCL;
  float* rsv = sm + SM_RSV;

  int t = threadIdx.x;
  int s = blockIdx.z;
  int bh = blockIdx.y; int b = bh>>3, h = bh&7;
  int i0 = blockIdx.x << 6;
  size_t rbase = ((size_t)bh)<<10;

  const float* qkv_q  = (s==0) ? qkv0 : qkv1;
  const float* qkv_kv = (s==0) ? qkv1 : qkv0;
  const float* LK     = (s==0) ? lk0  : lk1;
  const float* LQ     = (s==0) ? lq0  : lq1;
  float* out          = (s==0) ? att0 : att1;

  const float* qb = qkv_q  + (size_t)(b<<10)*QKVD + (h<<6);
  const float* kb = qkv_kv + (size_t)(b<<10)*QKVD + (h<<6) + 512;
  const float* vb = qkv_kv + (size_t)(b<<10)*QKVD + (h<<6) + 1024;

  // stage Q (tf32), LK rows, tvs (zero-padded), init sb/mrow
  #pragma unroll
  for (int it = 0; it < 4; it++){
    int f = t + (it<<8);
    int r = f >> 4, c4 = (f & 15) << 2;
    float4 qv = *(const float4*)(qb + (size_t)(i0+r)*QKVD + c4);
    qs[r*65+c4+0]=__uint_as_float(f2tf32(qv.x));
    qs[r*65+c4+1]=__uint_as_float(f2tf32(qv.y));
    qs[r*65+c4+2]=__uint_as_float(f2tf32(qv.z));
    qs[r*65+c4+3]=__uint_as_float(f2tf32(qv.w));
  }
  for (int f = t; f < 64*NBKT; f += 256){
    int r = f / NBKT, c = f - r*NBKT;
    lks[f] = LK[(rbase + i0 + r)*NBKT + c];
  }
  for (int f = t; f < 88*68; f += 256) tvs[f] = 0.f;
  for (int f = t; f < 64*88; f += 256) sb[f] = 0.f;
  if (t < 64) mrow[t] = -1e30f;
  __syncthreads();
  for (int f = t; f < NBKT*64; f += 256){
    int c = f >> 6, d = f & 63;
    tvs[c*68 + d] = __uint_as_float(f2tf32(tv[f]));
  }

  int warp = t >> 5, lane = t & 31;
  int g = lane >> 2, tg = lane & 3;
  int wm = (warp >> 2) << 5;
  int wn = (warp & 3) << 4;

  float acc[2][2][4];
  #pragma unroll
  for (int mt=0;mt<2;mt++)
    #pragma unroll
    for (int nt=0;nt<2;nt++)
      #pragma unroll
      for (int c=0;c<4;c++) acc[mt][nt][c]=0.f;

  int sr = t >> 2;                // scatter/softmax row
  int q0s = (t & 3) << 4;         // 16 cols per thread
  int iglob = i0 + sr;
  int syi = iglob >> 5, sxi = iglob & 31;

  for (int jt = 0; jt < 16; jt++){
    int j0 = jt << 6;
    // stage K, V (tf32) + LQ rows of this j-tile
    #pragma unroll
    for (int it = 0; it < 4; it++){
      int f = t + (it<<8);
      int r = f >> 4, c4 = (f & 15) << 2;
      float4 kv = *(const float4*)(kb + (size_t)(j0+r)*QKVD + c4);
      float4 vv = *(const float4*)(vb + (size_t)(j0+r)*QKVD + c4);
      ks[r*65+c4+0]=__uint_as_float(f2tf32(kv.x));
      ks[r*65+c4+1]=__uint_as_float(f2tf32(kv.y));
      ks[r*65+c4+2]=__uint_as_float(f2tf32(kv.z));
      ks[r*65+c4+3]=__uint_as_float(f2tf32(kv.w));
      vs[r*65+c4+0]=__uint_as_float(f2tf32(vv.x));
      vs[r*65+c4+1]=__uint_as_float(f2tf32(vv.y));
      vs[r*65+c4+2]=__uint_as_float(f2tf32(vv.z));
      vs[r*65+c4+3]=__uint_as_float(f2tf32(vv.w));
    }
    for (int f = t; f < 64*NBKT; f += 256){
      int r = f / NBKT, c = f - r*NBKT;
      lqs[f] = LQ[(rbase + j0 + r)*NBKT + c];
    }
    __syncthreads();

    // QK^T mma
    float sacc[2][2][4];
    #pragma unroll
    for (int mt=0;mt<2;mt++)
      #pragma unroll
      for (int nt=0;nt<2;nt++)
        #pragma unroll
        for (int c=0;c<4;c++) sacc[mt][nt][c]=0.f;
    #pragma unroll
    for (int kk = 0; kk < 64; kk += 8){
      uint32_t af[2][4], bf[2][2];
      #pragma unroll
      for (int mt = 0; mt < 2; mt++){
        int r0 = wm + (mt<<4) + g;
        af[mt][0] = __float_as_uint(qs[ r0   *65 + kk+tg  ]);
        af[mt][1] = __float_as_uint(qs[(r0+8)*65 + kk+tg  ]);
        af[mt][2] = __float_as_uint(qs[ r0   *65 + kk+tg+4]);
        af[mt][3] = __float_as_uint(qs[(r0+8)*65 + kk+tg+4]);
      }
      #pragma unroll
      for (int nt = 0; nt < 2; nt++){
        int n = wn + (nt<<3) + g;
        bf[nt][0] = __float_as_uint(ks[n*65 + kk+tg  ]);
        bf[nt][1] = __float_as_uint(ks[n*65 + kk+tg+4]);
      }
      #pragma unroll
      for (int mt = 0; mt < 2; mt++)
        #pragma unroll
        for (int nt = 0; nt < 2; nt++)
          mma_tf32(sacc[mt][nt], af[mt], bf[nt]);
    }

    // bias add -> ps (raw logits)
    #pragma unroll
    for (int mt = 0; mt < 2; mt++){
      #pragma unroll
      for (int hh = 0; hh < 2; hh++){
        int il = wm + (mt<<4) + g + (hh<<3);
        int i = i0 + il;
        int yi = i >> 5, xi = i & 31;
        const float* lkrow = lks + il*NBKT;
        #pragma unroll
        for (int nt = 0; nt < 2; nt++){
          int jl = wn + (nt<<3) + (tg<<1);
          int j = j0 + jl;
          int dy0 = yi - (j>>5),     dx0 = xi - (j&31);
          int dy1 = yi - ((j+1)>>5), dx1 = xi - ((j+1)&31);
          int bkt0 = ((int)c_pidx[dy0+31]+4)*9 + ((int)c_pidx[dx0+31]+4);
          int bkt1 = ((int)c_pidx[dy1+31]+4)*9 + ((int)c_pidx[dx1+31]+4);
          float v0 = sacc[mt][nt][hh*2+0]*0.125f + lkrow[bkt0] + lqs[jl*NBKT + 80 - bkt0];
          float v1 = sacc[mt][nt][hh*2+1]*0.125f + lkrow[bkt1] + lqs[(jl+1)*NBKT + 80 - bkt1];
          ps[il*65 + jl]   = v0;
          ps[il*65 + jl+1] = v1;
        }
      }
    }
    __syncthreads();

    // online softmax: per-row tile max via 4-lane reduce
    float tmax = -1e30f;
    #pragma unroll
    for (int q = 0; q < 16; q++) tmax = fmaxf(tmax, ps[sr*65 + q0s + q]);
    tmax = fmaxf(tmax, __shfl_xor_sync(0xffffffffu, tmax, 1));
    tmax = fmaxf(tmax, __shfl_xor_sync(0xffffffffu, tmax, 2));
    float m_old = mrow[sr];
    float m_new = fmaxf(m_old, tmax);
    float dm = m_old - m_new;
    float sc = (dm < -80.f) ? 0.f : fexp(dm);
    // rescale this row's bucket sums
    for (int c = (t&3); c < NBKT; c += 4) sb[sr*88 + c] *= sc;
    // exp in place (tf32-rounded)
    #pragma unroll
    for (int q = 0; q < 16; q++){
      int idx = sr*65 + q0s + q;
      ps[idx] = __uint_as_float(f2tf32(fexp(ps[idx] - m_new)));
    }
    __syncwarp();
    // run-length aggregated scatter
    {
      float runv = 0.f; int runb = -1;
      #pragma unroll
      for (int q = 0; q < 16; q++){
        int jj = q0s + q;
        int j = j0 + jj;
        int dy = syi - (j>>5), dx = sxi - (j&31);
        int bkt = ((int)c_pidx[dy+31]+4)*9 + ((int)c_pidx[dx+31]+4);
        float pvv = ps[sr*65 + jj];
        if (bkt == runb) runv += pvv;
        else {
          if (runb >= 0) atomicAdd(&sb[sr*88 + runb], runv);
          runb = bkt; runv = pvv;
        }
      }
      atomicAdd(&sb[sr*88 + runb], runv);
    }
    if ((t & 3) == 0){ mrow[sr] = m_new; scl[sr] = sc; }
    __syncthreads();

    // rescale acc, then PV mma
    #pragma unroll
    for (int mt = 0; mt < 2; mt++){
      #pragma unroll
      for (int hh = 0; hh < 2; hh++){
        float s2 = scl[wm + (mt<<4) + g + (hh<<3)];
        #pragma unroll
        for (int nt = 0; nt < 2; nt++){
          acc[mt][nt][hh*2+0] *= s2;
          acc[mt][nt][hh*2+1] *= s2;
        }
      }
    }
    #pragma unroll
    for (int kk = 0; kk < 64; kk += 8){
      uint32_t af[2][4], bf[2][2];
      #pragma unroll
      for (int mt = 0; mt < 2; mt++){
        int r0 = wm + (mt<<4) + g;
        af[mt][0] = __float_as_uint(ps[ r0   *65 + kk+tg  ]);
        af[mt][1] = __float_as_uint(ps[(r0+8)*65 + kk+tg  ]);
        af[mt][2] = __float_as_uint(ps[ r0   *65 + kk+tg+4]);
        af[mt][3] = __float_as_uint(ps[(r0+8)*65 + kk+tg+4]);
      }
      #pragma unroll
      for (int nt = 0; nt < 2; nt++){
        int n = wn + (nt<<3) + g;
        bf[nt][0] = __float_as_uint(vs[(kk+tg  )*65 + n]);
        bf[nt][1] = __float_as_uint(vs[(kk+tg+4)*65 + n]);
      }
      #pragma unroll
      for (int mt = 0; mt < 2; mt++)
        #pragma unroll
        for (int nt = 0; nt < 2; nt++)
          mma_tf32(acc[mt][nt], af[mt], bf[nt]);
    }
    __syncthreads();
  }

  // normalizers from bucket sums
  if (t < 64){
    float ssum = 0.f;
    #pragma unroll
    for (int c = 0; c < NBKT; c++) ssum += sb[t*88 + c];
    rsv[t] = 1.0f / ssum;
  }

  // tv-table term: acc += SB(64x88) @ tvs(88x64)
  #pragma unroll
  for (int kk = 0; kk < 88; kk += 8){
    uint32_t af[2][4], bf[2][2];
    #pragma unroll
    for (int mt = 0; mt < 2; mt++){
      int r0 = wm + (mt<<4) + g;
      af[mt][0] = __float_as_uint(sb[ r0   *88 + kk+tg  ]);
      af[mt][1] = __float_as_uint(sb[(r0+8)*88 + kk+tg  ]);
      af[mt][2] = __float_as_uint(sb[ r0   *88 + kk+tg+4]);
      af[mt][3] = __float_as_uint(sb[(r0+8)*88 + kk+tg+4]);
    }
    #pragma unroll
    for (int nt = 0; nt < 2; nt++){
      int n = wn + (nt<<3) + g;
      bf[nt][0] = __float_as_uint(tvs[(kk+tg  )*68 + n]);
      bf[nt][1] = __float_as_uint(tvs[(kk+tg+4)*68 + n]);
    }
    #pragma unroll
    for (int mt = 0; mt < 2; mt++)
      #pragma unroll
      for (int nt = 0; nt < 2; nt++)
        mma_tf32(acc[mt][nt], af[mt], bf[nt]);
  }
  __syncthreads();

  // epilogue: normalize, write
  #pragma unroll
  for (int mt = 0; mt < 2; mt++){
    #pragma unroll
    for (int hh = 0; hh < 2; hh++){
      int r = wm + (mt<<4) + g + (hh<<3);
      float inv = rsv[r];
      #pragma unroll
      for (int nt = 0; nt < 2; nt++){
        int col = wn + (nt<<3) + (tg<<1);
        float o0 = acc[mt][nt][hh*2+0] * inv;
        float o1 = acc[mt][nt][hh*2+1] * inv;
        float* op = out + ((size_t)(b<<10) + i0 + r)*CDIM + (h<<6) + col;
        *(float2*)op = make_float2(o0, o1);
      }
    }
  }
}

// ---------------- launch ----------------------------------------------------
extern "C" void kernel_launch(void* const* d_in, const int* in_sizes, int n_in,
                              void* d_out, int out_size)
{
  const float* x0     = (const float*)d_in[0];
  const float* x1     = (const float*)d_in[1];
  const float* ln00_g = (const float*)d_in[2];
  const float* ln00_b = (const float*)d_in[3];
  const float* ln01_g = (const float*)d_in[4];
  const float* ln01_b = (const float*)d_in[5];
  const float* ln10_g = (const float*)d_in[6];
  const float* ln10_b = (const float*)d_in[7];
  const float* ln11_g = (const float*)d_in[8];
  const float* ln11_b = (const float*)d_in[9];
  const float* w_qkv0 = (const float*)d_in[10];
  const float* b_qkv0 = (const float*)d_in[11];
  const float* w_qkv1 = (const float*)d_in[12];
  const float* b_qkv1 = (const float*)d_in[13];
  const float* w_proj = (const float*)d_in[14];
  const float* b_proj = (const float*)d_in[15];
  const float* table_q= (const float*)d_in[16];
  const float* table_k= (const float*)d_in[17];
  const float* table_v= (const float*)d_in[18];
  const float* w_fc1_0= (const float*)d_in[19];
  const float* b_fc1_0= (const float*)d_in[20];
  const float* w_fc2_0= (const float*)d_in[21];
  const float* b_fc2_0= (const float*)d_in[22];
  const float* w_fc1_1= (const float*)d_in[23];
  const float* b_fc1_1= (const float*)d_in[24];
  const float* w_fc2_1= (const float*)d_in[25];
  const float* b_fc2_1= (const float*)d_in[26];

  float* out0 = (float*)d_out;
  float* out1 = (float*)d_out + (size_t)ROWS*CDIM;

  float *ln0, *ln1, *qkv0, *qkv1, *att0, *att1, *lk0, *lk1, *lq0, *lq1;
  float *hid0, *hid1;
  cudaGetSymbolAddress((void**)&ln0,  g_ln);     ln1  = ln0  + (size_t)ROWS*CDIM;
  cudaGetSymbolAddress((void**)&qkv0, g_qkv);    qkv1 = qkv0 + (size_t)ROWS*QKVD;
  cudaGetSymbolAddress((void**)&att0, g_att);    att1 = att0 + (size_t)ROWS*CDIM;
  cudaGetSymbolAddress((void**)&lk0,  g_lk);     lk1  = lk0  + (size_t)BHN*NBKT;
  cudaGetSymbolAddress((void**)&lq0,  g_lq);     lq1  = lq0  + (size_t)BHN*NBKT;
  cudaGetSymbolAddress((void**)&hid0, g_hid);    hid1 = hid0 + (size_t)ROWS*HID;

  const int FUSED_SMEM = FUSED_SMEM_FLOATS * 4;   // 155264 B
  static int attr_done = 0;
  if (!attr_done){
    cudaFuncSetAttribute(fused_attn_kernel, cudaFuncAttributeMaxDynamicSharedMemorySize, FUSED_SMEM);
    attr_done = 1;
  }

  // 1. LN
  ln_kernel<<<ROWS, 128>>>(x0, ln00_g, ln00_b, ln0);
  ln_kernel<<<ROWS, 128>>>(x1, ln01_g, ln01_b, ln1);

  // 2. qkv GEMMs
  dim3 gqkv(QKVD/128, ROWS/128);
  sgemm_tf32_kernel<<<gqkv, 256>>>(ln0, w_qkv0, b_qkv0, nullptr, qkv0, ROWS, QKVD, CDIM, 0);
  sgemm_tf32_kernel<<<gqkv, 256>>>(ln1, w_qkv1, b_qkv1, nullptr, qkv1, ROWS, QKVD, CDIM, 0);

  // 3. bias tables
  dim3 gbt(BHN/64, 2, 2);
  biastab_kernel<<<gbt, 256>>>(qkv0, qkv1, table_q, table_k, lk0, lk1, lq0, lq1);

  // 4. fused attention (both streams in one launch)
  dim3 gfa(16, 32, 2);
  fused_attn_kernel<<<gfa, 256, FUSED_SMEM>>>(qkv0, qkv1, lk0, lk1, lq0, lq1,
                                              table_v, att0, att1);

  // 5. proj + residual
  dim3 gproj(CDIM/128, ROWS/128);
  sgemm_tf32_kernel<<<gproj, 256>>>(att0, w_proj, b_proj, x0, out0, ROWS, CDIM, CDIM, 0);
  sgemm_tf32_kernel<<<gproj, 256>>>(att1, w_proj, b_proj, x1, out1, ROWS, CDIM, CDIM, 0);

  // 6. MLP
  ln_kernel<<<ROWS, 128>>>(out0, ln10_g, ln10_b, ln0);
  ln_kernel<<<ROWS, 128>>>(out1, ln11_g, ln11_b, ln1);

  dim3 gfc1(HID/128, ROWS/128);
  sgemm_tf32_kernel<<<gfc1, 256>>>(ln0, w_fc1_0, b_fc1_0, nullptr, hid0, ROWS, HID, CDIM, 1);
  sgemm_tf32_kernel<<<gfc1, 256>>>(ln1, w_fc1_1, b_fc1_1, nullptr, hid1, ROWS, HID, CDIM, 1);

  dim3 gfc2(CDIM/128, ROWS/128);
  sgemm_tf32_kernel<<<gfc2, 256>>>(hid0, w_fc2_0, b_fc2_0, out0, out0, ROWS, CDIM, HID, 0);
  sgemm_tf32_kernel<<<gfc2, 256>>>(hid1, w_fc2_1, b_fc2_1, out1, out1, ROWS, CDIM, HID, 0);
}

// round 9
// speedup vs baseline: 1.5621x; 1.5621x over previous
#include <cuda_runtime.h>
#include <cuda_bf16.h>
#include <math.h>
#include <stdint.h>

// ---------------- problem constants ----------------
#define ROWS 4096        // B*N
#define CDIM 512
#define QKVD 1536
#define HID  2048
#define NHEAD 8
#define HD   64
#define NQ   1024
#define BHN  32768       // B*H*N
#define NBKT 81

// ---------------- device scratch ----------------
__device__ float g_ln    [2][ROWS*CDIM];
__device__ float g_qkv   [2][ROWS*QKVD];
__device__ float g_att   [2][ROWS*CDIM];
__device__ float g_lk    [2][(size_t)BHN*NBKT];
__device__ float g_lq    [2][(size_t)BHN*NBKT];
__device__ float g_logits[2][(size_t)32*NQ*NQ];
__device__ float g_ml    [2][BHN];
__device__ float g_hid   [2][(size_t)ROWS*HID];

__constant__ signed char c_pidx[63] = {
  -4,-4,-4,-4,-4,-4,-4,-4,-4,-4,-4,-4,-4,-4,-4,-4,-4,-4,-4,-4,-4,
  -3,-3,-3,-3,-3,-3,-3,
  -2,-2,
  -1,
   0,
   1,
   2, 2,
   3, 3, 3, 3, 3, 3, 3,
   4, 4, 4, 4, 4, 4, 4, 4, 4, 4, 4, 4, 4, 4, 4, 4, 4, 4, 4, 4, 4
};

__device__ __forceinline__ float fexp(float x){
  float y = x * 1.4426950408889634f;
  float n = rintf(y);
  float f = y - n;
  float p =           1.3333558e-3f;
  p = fmaf(p, f, 9.6181291e-3f);
  p = fmaf(p, f, 5.5504108e-2f);
  p = fmaf(p, f, 2.4022650e-1f);
  p = fmaf(p, f, 6.9314718e-1f);
  p = fmaf(p, f, 1.0f);
  int ni = (int)n;
  return p * __int_as_float((ni + 127) << 23);
}

__device__ __forceinline__ uint32_t f2tf32(float v){
  uint32_t r;
  asm("cvt.rna.tf32.f32 %0, %1;" : "=r"(r) : "f"(v));
  return r;
}

__device__ __forceinline__ void mma_tf32(float* c, const uint32_t* a, const uint32_t* b){
  asm volatile(
    "mma.sync.aligned.m16n8k8.row.col.f32.tf32.tf32.f32 "
    "{%0,%1,%2,%3}, {%4,%5,%6,%7}, {%8,%9}, {%0,%1,%2,%3};"
    : "+f"(c[0]), "+f"(c[1]), "+f"(c[2]), "+f"(c[3])
    : "r"(a[0]), "r"(a[1]), "r"(a[2]), "r"(a[3]), "r"(b[0]), "r"(b[1]));
}

__device__ __forceinline__ void cp16(uint32_t dst, const float* src){
  asm volatile("cp.async.cg.shared.global [%0], [%1], 16;\n" :: "r"(dst), "l"(src));
}

// ---------------- layernorm ------------------------------------------------
__global__ void ln_kernel(const float* __restrict__ x, const float* __restrict__ gam,
                          const float* __restrict__ bet, float* __restrict__ y)
{
  int row = blockIdx.x;
  int t = threadIdx.x;
  const float* xr = x + (size_t)row * CDIM;
  float4 v = *(const float4*)(xr + t*4);
  float s  = v.x + v.y + v.z + v.w;
  float s2 = v.x*v.x + v.y*v.y + v.z*v.z + v.w*v.w;
  #pragma unroll
  for (int o = 16; o > 0; o >>= 1){
    s  += __shfl_xor_sync(0xffffffffu, s , o);
    s2 += __shfl_xor_sync(0xffffffffu, s2, o);
  }
  __shared__ float rs[4], rq[4];
  if ((t & 31) == 0){ rs[t>>5] = s; rq[t>>5] = s2; }
  __syncthreads();
  s  = rs[0]+rs[1]+rs[2]+rs[3];
  s2 = rq[0]+rq[1]+rq[2]+rq[3];
  float mu   = s  * (1.0f/CDIM);
  float var  = s2 * (1.0f/CDIM) - mu*mu;
  float rstd = rsqrtf(var + 1e-5f);
  float4 g4 = *(const float4*)(gam + t*4);
  float4 b4 = *(const float4*)(bet + t*4);
  float4 o4;
  o4.x = (v.x-mu)*rstd*g4.x + b4.x;
  o4.y = (v.y-mu)*rstd*g4.y + b4.y;
  o4.z = (v.z-mu)*rstd*g4.z + b4.z;
  o4.w = (v.w-mu)*rstd*g4.w + b4.w;
  *(float4*)(y + (size_t)row*CDIM + t*4) = o4;
}

// ---------------- tf32 tensor-core GEMM, cp.async double-buffered ----------
// 128x128x16 tile, 8 warps (2x4). A staged [m][20], B staged [k][132].
__global__ void __launch_bounds__(256, 2) sgemm_tf32_kernel(
    const float* __restrict__ A, const float* __restrict__ Bm,
    const float* __restrict__ bias, const float* __restrict__ resid,
    float* __restrict__ C, int M, int N, int K, int gelu)
{
  __shared__ float As[2][128*20];
  __shared__ float Bs[2][16*132];
  int t = threadIdx.x;
  int bn = blockIdx.x * 128;
  int bm = blockIdx.y * 128;
  int warp = t >> 5, lane = t & 31;
  int wm = (warp >> 2) << 6;
  int wn = (warp & 3) << 5;
  int g  = lane >> 2;
  int tg = lane & 3;

  float acc[4][4][4];
  #pragma unroll
  for (int mt=0;mt<4;mt++)
    #pragma unroll
    for (int nt=0;nt<4;nt++)
      #pragma unroll
      for (int c=0;c<4;c++) acc[mt][nt][c] = 0.f;

  const float* Ag = A + (size_t)bm * K;
  const float* Bg = Bm + bn;

  uint32_t asb[2], bsb[2];
  asb[0] = (uint32_t)__cvta_generic_to_shared(&As[0][0]);
  asb[1] = (uint32_t)__cvta_generic_to_shared(&As[1][0]);
  bsb[0] = (uint32_t)__cvta_generic_to_shared(&Bs[0][0]);
  bsb[1] = (uint32_t)__cvta_generic_to_shared(&Bs[1][0]);

  // per-thread chunk coords (2 x 16B for A, 2 x 16B for B per tile)
  int ar[2], as4[2], bkr[2], bnc[2];
  #pragma unroll
  for (int i = 0; i < 2; i++){
    int c = t + (i<<8);
    ar[i]  = c >> 2;  as4[i] = (c & 3) << 2;
    bkr[i] = c >> 5;  bnc[i] = (c & 31) << 2;
  }

  int ntiles = K >> 4;
  // prologue: issue tile 0
  #pragma unroll
  for (int i = 0; i < 2; i++){
    cp16(asb[0] + ((ar[i]*20 + as4[i])<<2), Ag + (size_t)ar[i]*K + as4[i]);
    cp16(bsb[0] + ((bkr[i]*132 + bnc[i])<<2), Bg + (size_t)bkr[i]*N + bnc[i]);
  }
  asm volatile("cp.async.commit_group;\n");

  for (int it = 0; it < ntiles; it++){
    int buf = it & 1;
    if (it + 1 < ntiles){
      int k0 = (it+1) << 4;
      int nb = (it+1) & 1;
      #pragma unroll
      for (int i = 0; i < 2; i++){
        cp16(asb[nb] + ((ar[i]*20 + as4[i])<<2), Ag + (size_t)ar[i]*K + k0 + as4[i]);
        cp16(bsb[nb] + ((bkr[i]*132 + bnc[i])<<2), Bg + (size_t)(k0 + bkr[i])*N + bnc[i]);
      }
    }
    asm volatile("cp.async.commit_group;\n");
    asm volatile("cp.async.wait_group 1;\n");
    __syncthreads();

    const float* Ab = As[buf];
    const float* Bb = Bs[buf];
    #pragma unroll
    for (int ks = 0; ks < 16; ks += 8){
      uint32_t af[4][4], bf[4][2];
      #pragma unroll
      for (int mt = 0; mt < 4; mt++){
        int m = wm + (mt<<4) + g;
        af[mt][0] = __float_as_uint(Ab[ m   *20 + ks+tg  ]);
        af[mt][1] = __float_as_uint(Ab[(m+8)*20 + ks+tg  ]);
        af[mt][2] = __float_as_uint(Ab[ m   *20 + ks+tg+4]);
        af[mt][3] = __float_as_uint(Ab[(m+8)*20 + ks+tg+4]);
      }
      #pragma unroll
      for (int nt = 0; nt < 4; nt++){
        int n = wn + (nt<<3) + g;
        bf[nt][0] = __float_as_uint(Bb[(ks+tg  )*132 + n]);
        bf[nt][1] = __float_as_uint(Bb[(ks+tg+4)*132 + n]);
      }
      #pragma unroll
      for (int mt = 0; mt < 4; mt++)
        #pragma unroll
        for (int nt = 0; nt < 4; nt++)
          mma_tf32(acc[mt][nt], af[mt], bf[nt]);
    }
    __syncthreads();
  }

  #pragma unroll
  for (int mt = 0; mt < 4; mt++){
    int row0 = bm + wm + (mt<<4) + g;
    #pragma unroll
    for (int nt = 0; nt < 4; nt++){
      int col = bn + wn + (nt<<3) + (tg<<1);
      float b0 = bias[col], b1 = bias[col+1];
      #pragma unroll
      for (int h = 0; h < 2; h++){
        int row = row0 + (h<<3);
        float r0 = acc[mt][nt][h*2+0] + b0;
        float r1 = acc[mt][nt][h*2+1] + b1;
        if (gelu){
          r0 = 0.5f*r0*(1.0f + erff(r0*0.70710678f));
          r1 = 0.5f*r1*(1.0f + erff(r1*0.70710678f));
        }
        if (resid){
          const float2 rr = *(const float2*)(resid + (size_t)row*N + col);
          r0 += rr.x; r1 += rr.y;
        }
        *(float2*)(C + (size_t)row*N + col) = make_float2(r0, r1);
      }
    }
  }
}

// ---------------- bias tables as tiled GEMM ---------------------------------
__global__ void __launch_bounds__(256) biastab_kernel(
    const float* __restrict__ qkv0, const float* __restrict__ qkv1,
    const float* __restrict__ tq, const float* __restrict__ tk,
    float* __restrict__ lk0, float* __restrict__ lk1,
    float* __restrict__ lq0, float* __restrict__ lq1)
{
  __shared__ float qs[64*65];
  __shared__ float tabT[64*84];

  int t = threadIdx.x;
  int s = blockIdx.z, which = blockIdx.y;
  int base = blockIdx.x << 6;
  const float* src;
  float scl;
  if (which == 0){ src = (s == 0 ? qkv0 : qkv1);       scl = 1.0f;   }
  else           { src = (s == 0 ? qkv1 : qkv0) + 512; scl = 0.125f; }
  const float* tab = (which == 0) ? tk : tq;

  for (int idx = t; idx < NBKT*64; idx += 256){
    int c = idx >> 6, d = idx & 63;
    tabT[d*84 + c] = tab[idx];
  }
  #pragma unroll
  for (int it = 0; it < 4; it++){
    int f = t + (it<<8);
    int r = f >> 4, c4 = (f & 15) << 2;
    int rid = base + r;
    int bh = rid >> 10, n = rid & 1023;
    int b = bh >> 3, h = bh & 7;
    float4 v = *(const float4*)(src + (size_t)((b<<10)+n)*QKVD + (h<<6) + c4);
    qs[r*65+c4+0] = scl*v.x; qs[r*65+c4+1] = scl*v.y;
    qs[r*65+c4+2] = scl*v.z; qs[r*65+c4+3] = scl*v.w;
  }
  __syncthreads();

  int tx = t & 31, ty = t >> 5;
  float acc[8][3];
  #pragma unroll
  for (int i=0;i<8;i++){ acc[i][0]=0.f; acc[i][1]=0.f; acc[i][2]=0.f; }

  #pragma unroll 8
  for (int k = 0; k < 64; k++){
    float b0 = tabT[k*84 + tx];
    float b1 = tabT[k*84 + tx + 32];
    float b2 = (tx < 17) ? tabT[k*84 + tx + 64] : 0.f;
    #pragma unroll
    for (int i = 0; i < 8; i++){
      float a = qs[((ty<<3)+i)*65 + k];
      acc[i][0] = fmaf(a, b0, acc[i][0]);
      acc[i][1] = fmaf(a, b1, acc[i][1]);
      acc[i][2] = fmaf(a, b2, acc[i][2]);
    }
  }

  float* dstbase = (which == 0) ? (s == 0 ? lk0 : lk1) : (s == 0 ? lq0 : lq1);
  #pragma unroll
  for (int i = 0; i < 8; i++){
    int rid = base + (ty<<3) + i;
    float* dst = dstbase + (size_t)rid*NBKT;
    dst[tx]      = acc[i][0];
    dst[tx + 32] = acc[i][1];
    if (tx < 17) dst[tx + 64] = acc[i][2];
  }
}

// ---------------- attention logits: tensor-core 64x64 tile (merged streams) -
__global__ void __launch_bounds__(256) logits_kernel(
    const float* __restrict__ qkv0, const float* __restrict__ qkv1,
    const float* __restrict__ lk0, const float* __restrict__ lk1,
    const float* __restrict__ lq0, const float* __restrict__ lq1,
    float* __restrict__ lg0, float* __restrict__ lg1)
{
  extern __shared__ float sm[];
  float* qs  = sm;           // [64][65]
  float* ksm = sm + 4160;    // [64][65]
  float* lks = sm + 8320;    // [64][81]
  float* lqs = sm + 13504;   // [64][81]

  int t = threadIdx.x;
  int z = blockIdx.z;
  int s = z >> 5;
  int bh = z & 31; int b = bh>>3, h = bh&7;
  int i0 = blockIdx.y<<6, j0 = blockIdx.x<<6;
  size_t rbase = ((size_t)bh)<<10;
  const float* qkv_q  = (s==0) ? qkv0 : qkv1;
  const float* qkv_kv = (s==0) ? qkv1 : qkv0;
  const float* LK     = (s==0) ? lk0  : lk1;
  const float* LQ     = (s==0) ? lq0  : lq1;
  float* S            = (s==0) ? lg0  : lg1;

  const float* qb = qkv_q  + (size_t)(b<<10)*QKVD + (h<<6);
  const float* kb = qkv_kv + (size_t)(b<<10)*QKVD + (h<<6) + 512;
  #pragma unroll
  for (int it = 0; it < 4; it++){
    int f = t + (it<<8);
    int r = f >> 4, c4 = (f & 15) << 2;
    float4 qv = *(const float4*)(qb + (size_t)(i0+r)*QKVD + c4);
    float4 kv = *(const float4*)(kb + (size_t)(j0+r)*QKVD + c4);
    qs[r*65+c4+0]=__uint_as_float(f2tf32(qv.x));
    qs[r*65+c4+1]=__uint_as_float(f2tf32(qv.y));
    qs[r*65+c4+2]=__uint_as_float(f2tf32(qv.z));
    qs[r*65+c4+3]=__uint_as_float(f2tf32(qv.w));
    ksm[r*65+c4+0]=__uint_as_float(f2tf32(kv.x));
    ksm[r*65+c4+1]=__uint_as_float(f2tf32(kv.y));
    ksm[r*65+c4+2]=__uint_as_float(f2tf32(kv.z));
    ksm[r*65+c4+3]=__uint_as_float(f2tf32(kv.w));
  }
  for (int f = t; f < 64*NBKT; f += 256){
    int r = f / NBKT, c = f - r*NBKT;
    lks[f] = LK[(rbase + i0 + r)*NBKT + c];
    lqs[f] = LQ[(rbase + j0 + r)*NBKT + c];
  }
  __syncthreads();

  int warp = t >> 5, lane = t & 31;
  int g = lane >> 2, tg = lane & 3;
  int wm = (warp >> 2) << 5;
  int wn = (warp & 3) << 4;

  float acc[2][2][4];
  #pragma unroll
  for (int mt=0;mt<2;mt++)
    #pragma unroll
    for (int nt=0;nt<2;nt++)
      #pragma unroll
      for (int c=0;c<4;c++) acc[mt][nt][c]=0.f;

  #pragma unroll
  for (int ks = 0; ks < 64; ks += 8){
    uint32_t af[2][4], bf[2][2];
    #pragma unroll
    for (int mt = 0; mt < 2; mt++){
      int r0 = wm + (mt<<4) + g;
      af[mt][0] = __float_as_uint(qs[ r0   *65 + ks+tg  ]);
      af[mt][1] = __float_as_uint(qs[(r0+8)*65 + ks+tg  ]);
      af[mt][2] = __float_as_uint(qs[ r0   *65 + ks+tg+4]);
      af[mt][3] = __float_as_uint(qs[(r0+8)*65 + ks+tg+4]);
    }
    #pragma unroll
    for (int nt = 0; nt < 2; nt++){
      int n = wn + (nt<<3) + g;
      bf[nt][0] = __float_as_uint(ksm[n*65 + ks+tg  ]);
      bf[nt][1] = __float_as_uint(ksm[n*65 + ks+tg+4]);
    }
    #pragma unroll
    for (int mt = 0; mt < 2; mt++)
      #pragma unroll
      for (int nt = 0; nt < 2; nt++)
        mma_tf32(acc[mt][nt], af[mt], bf[nt]);
  }

  #pragma unroll
  for (int mt = 0; mt < 2; mt++){
    #pragma unroll
    for (int hh = 0; hh < 2; hh++){
      int il = wm + (mt<<4) + g + (hh<<3);
      int i = i0 + il;
      int yi = i >> 5, xi = i & 31;
      const float* lkrow = lks + il*NBKT;
      #pragma unroll
      for (int nt = 0; nt < 2; nt++){
        int jl = wn + (nt<<3) + (tg<<1);
        int j = j0 + jl;
        int dy0 = yi - (j>>5),     dx0 = xi - (j&31);
        int dy1 = yi - ((j+1)>>5), dx1 = xi - ((j+1)&31);
        int bkt0 = ((int)c_pidx[dy0+31]+4)*9 + ((int)c_pidx[dx0+31]+4);
        int bkt1 = ((int)c_pidx[dy1+31]+4)*9 + ((int)c_pidx[dx1+31]+4);
        float v0 = acc[mt][nt][hh*2+0]*0.125f + lkrow[bkt0] + lqs[jl*NBKT + 80 - bkt0];
        float v1 = acc[mt][nt][hh*2+1]*0.125f + lkrow[bkt1] + lqs[(jl+1)*NBKT + 80 - bkt1];
        *(float2*)(S + (rbase + i)*NQ + j) = make_float2(v0, v1);
      }
    }
  }
}

// ---------------- row max only (merged streams) -----------------------------
__global__ void smax_kernel(const float* __restrict__ Sbase, float* __restrict__ mlbase)
{
  int rid = blockIdx.x;          // 0..65535; stream = rid>>15
  int t = threadIdx.x;
  const float* S = Sbase + ((size_t)(rid >> 15)) * ((size_t)32*NQ*NQ);
  float* ml = mlbase + ((rid >> 15) ? BHN : 0);
  int row = rid & 32767;
  const float4 a = ((const float4*)(S + (size_t)row*NQ))[t];
  float m = fmaxf(fmaxf(a.x,a.y), fmaxf(a.z,a.w));
  #pragma unroll
  for (int o=16;o>0;o>>=1) m = fmaxf(m, __shfl_xor_sync(0xffffffffu,m,o));
  __shared__ float rm[8];
  if ((t&31)==0) rm[t>>5] = m;
  __syncthreads();
  if (t==0){
    m = rm[0];
    #pragma unroll
    for (int w=1;w<8;w++) m = fmaxf(m, rm[w]);
    ml[row] = m;
  }
}

// ---------------- PV: tensor-core 64x64 + scatter + tv-GEMM (merged) --------
__global__ void __launch_bounds__(256) pv_kernel(
    const float* __restrict__ lg0, const float* __restrict__ lg1,
    const float* __restrict__ ml0, const float* __restrict__ ml1,
    const float* __restrict__ qkv0, const float* __restrict__ qkv1,
    const float* __restrict__ tv,
    float* __restrict__ att0, float* __restrict__ att1)
{
  extern __shared__ float sm[];
  float* ps  = sm;            // [64][65]
  float* vs  = sm + 4160;     // [64][65]
  float* sb  = sm + 8320;     // [64][88]
  float* tvs = sm + 13952;    // [88][68]
  float* mrow= sm + 19936;    // [64]
  float* rsv = sm + 20000;    // [64]

  int t = threadIdx.x;
  int zy = blockIdx.y;
  int s = zy >> 5;
  int bh = zy & 31; int b = bh>>3, h = bh&7;
  int i0 = blockIdx.x << 6;
  size_t rb2 = (((size_t)bh)<<10) + i0;

  const float* S  = (s==0) ? lg0 : lg1;
  const float* ml = (s==0) ? ml0 : ml1;
  const float* qkv_kv = (s==0) ? qkv1 : qkv0;
  float* out = (s==0) ? att0 : att1;

  if (t < 64) mrow[t] = ml[rb2 + t];
  for (int f = t; f < 64*88; f += 256) sb[f] = 0.f;
  for (int f = t; f < 88*68; f += 256) tvs[f] = 0.f;
  __syncthreads();
  for (int f = t; f < NBKT*64; f += 256){
    int c = f >> 6, d = f & 63;
    tvs[c*68 + d] = __uint_as_float(f2tf32(tv[f]));
  }
  __syncthreads();

  int warp = t >> 5, lane = t & 31;
  int g = lane >> 2, tg = lane & 3;
  int wm = (warp >> 2) << 5;
  int wn = (warp & 3) << 4;

  float acc[2][2][4];
  #pragma unroll
  for (int mt=0;mt<2;mt++)
    #pragma unroll
    for (int nt=0;nt<2;nt++)
      #pragma unroll
      for (int c=0;c<4;c++) acc[mt][nt][c]=0.f;

  const float* vb = qkv_kv + ((size_t)(b<<10))*QKVD + (h<<6) + 1024;

  int sr = t >> 2;
  int q0 = (t & 3) << 4;
  int iglob = i0 + sr;
  int syi = iglob >> 5, sxi = iglob & 31;

  for (int jt = 0; jt < 16; jt++){
    int j0 = jt << 6;
    #pragma unroll
    for (int it = 0; it < 4; it++){
      int f = t + (it<<8);
      int r = f >> 4, c4 = (f&15)<<2;
      float4 sv = *(const float4*)(S + (rb2 + r)*NQ + j0 + c4);
      float m = mrow[r];
      ps[r*65+c4+0] = __uint_as_float(f2tf32(fexp(sv.x - m)));
      ps[r*65+c4+1] = __uint_as_float(f2tf32(fexp(sv.y - m)));
      ps[r*65+c4+2] = __uint_as_float(f2tf32(fexp(sv.z - m)));
      ps[r*65+c4+3] = __uint_as_float(f2tf32(fexp(sv.w - m)));
      float4 vv = *(const float4*)(vb + (size_t)(j0+r)*QKVD + c4);
      vs[r*65+c4+0]=__uint_as_float(f2tf32(vv.x));
      vs[r*65+c4+1]=__uint_as_float(f2tf32(vv.y));
      vs[r*65+c4+2]=__uint_as_float(f2tf32(vv.z));
      vs[r*65+c4+3]=__uint_as_float(f2tf32(vv.w));
    }
    __syncthreads();

    {
      float runv = 0.f; int runb = -1;
      #pragma unroll
      for (int q = 0; q < 16; q++){
        int jj = q0 + q;
        int j = j0 + jj;
        int dy = syi - (j>>5), dx = sxi - (j&31);
        int bkt = ((int)c_pidx[dy+31]+4)*9 + ((int)c_pidx[dx+31]+4);
        float pvv = ps[sr*65 + jj];
        if (bkt == runb) runv += pvv;
        else {
          if (runb >= 0) atomicAdd(&sb[sr*88 + runb], runv);
          runb = bkt; runv = pvv;
        }
      }
      atomicAdd(&sb[sr*88 + runb], runv);
    }

    #pragma unroll
    for (int ks = 0; ks < 64; ks += 8){
      uint32_t af[2][4], bf[2][2];
      #pragma unroll
      for (int mt = 0; mt < 2; mt++){
        int r0 = wm + (mt<<4) + g;
        af[mt][0] = __float_as_uint(ps[ r0   *65 + ks+tg  ]);
        af[mt][1] = __float_as_uint(ps[(r0+8)*65 + ks+tg  ]);
        af[mt][2] = __float_as_uint(ps[ r0   *65 + ks+tg+4]);
        af[mt][3] = __float_as_uint(ps[(r0+8)*65 + ks+tg+4]);
      }
      #pragma unroll
      for (int nt = 0; nt < 2; nt++){
        int n = wn + (nt<<3) + g;
        bf[nt][0] = __float_as_uint(vs[(ks+tg  )*65 + n]);
        bf[nt][1] = __float_as_uint(vs[(ks+tg+4)*65 + n]);
      }
      #pragma unroll
      for (int mt = 0; mt < 2; mt++)
        #pragma unroll
        for (int nt = 0; nt < 2; nt++)
          mma_tf32(acc[mt][nt], af[mt], bf[nt]);
    }
    __syncthreads();
  }

  if (t < 64){
    float ssum = 0.f;
    #pragma unroll
    for (int c = 0; c < NBKT; c++) ssum += sb[t*88 + c];
    rsv[t] = 1.0f / ssum;
  }

  #pragma unroll
  for (int ks = 0; ks < 88; ks += 8){
    uint32_t af[2][4], bf[2][2];
    #pragma unroll
    for (int mt = 0; mt < 2; mt++){
      int r0 = wm + (mt<<4) + g;
      af[mt][0] = __float_as_uint(sb[ r0   *88 + ks+tg  ]);
      af[mt][1] = __float_as_uint(sb[(r0+8)*88 + ks+tg  ]);
      af[mt][2] = __float_as_uint(sb[ r0   *88 + ks+tg+4]);
      af[mt][3] = __float_as_uint(sb[(r0+8)*88 + ks+tg+4]);
    }
    #pragma unroll
    for (int nt = 0; nt < 2; nt++){
      int n = wn + (nt<<3) + g;
      bf[nt][0] = __float_as_uint(tvs[(ks+tg  )*68 + n]);
      bf[nt][1] = __float_as_uint(tvs[(ks+tg+4)*68 + n]);
    }
    #pragma unroll
    for (int mt = 0; mt < 2; mt++)
      #pragma unroll
      for (int nt = 0; nt < 2; nt++)
        mma_tf32(acc[mt][nt], af[mt], bf[nt]);
  }
  __syncthreads();

  #pragma unroll
  for (int mt = 0; mt < 2; mt++){
    #pragma unroll
    for (int hh = 0; hh < 2; hh++){
      int r = wm + (mt<<4) + g + (hh<<3);
      float inv = rsv[r];
      #pragma unroll
      for (int nt = 0; nt < 2; nt++){
        int col = wn + (nt<<3) + (tg<<1);
        float o0 = acc[mt][nt][hh*2+0] * inv;
        float o1 = acc[mt][nt][hh*2+1] * inv;
        float* op = out + ((size_t)(b<<10) + i0 + r)*CDIM + (h<<6) + col;
        *(float2*)op = make_float2(o0, o1);
      }
    }
  }
}

// ---------------- launch ----------------------------------------------------
extern "C" void kernel_launch(void* const* d_in, const int* in_sizes, int n_in,
                              void* d_out, int out_size)
{
  const float* x0     = (const float*)d_in[0];
  const float* x1     = (const float*)d_in[1];
  const float* ln00_g = (const float*)d_in[2];
  const float* ln00_b = (const float*)d_in[3];
  const float* ln01_g = (const float*)d_in[4];
  const float* ln01_b = (const float*)d_in[5];
  const float* ln10_g = (const float*)d_in[6];
  const float* ln10_b = (const float*)d_in[7];
  const float* ln11_g = (const float*)d_in[8];
  const float* ln11_b = (const float*)d_in[9];
  const float* w_qkv0 = (const float*)d_in[10];
  const float* b_qkv0 = (const float*)d_in[11];
  const float* w_qkv1 = (const float*)d_in[12];
  const float* b_qkv1 = (const float*)d_in[13];
  const float* w_proj = (const float*)d_in[14];
  const float* b_proj = (const float*)d_in[15];
  const float* table_q= (const float*)d_in[16];
  const float* table_k= (const float*)d_in[17];
  const float* table_v= (const float*)d_in[18];
  const float* w_fc1_0= (const float*)d_in[19];
  const float* b_fc1_0= (const float*)d_in[20];
  const float* w_fc2_0= (const float*)d_in[21];
  const float* b_fc2_0= (const float*)d_in[22];
  const float* w_fc1_1= (const float*)d_in[23];
  const float* b_fc1_1= (const float*)d_in[24];
  const float* w_fc2_1= (const float*)d_in[25];
  const float* b_fc2_1= (const float*)d_in[26];

  float* out0 = (float*)d_out;
  float* out1 = (float*)d_out + (size_t)ROWS*CDIM;

  float *ln0, *ln1, *qkv0, *qkv1, *att0, *att1, *lk0, *lk1, *lq0, *lq1;
  float *lg0, *lg1, *ml0, *ml1, *hid0, *hid1;
  cudaGetSymbolAddress((void**)&ln0,  g_ln);     ln1  = ln0  + (size_t)ROWS*CDIM;
  cudaGetSymbolAddress((void**)&qkv0, g_qkv);    qkv1 = qkv0 + (size_t)ROWS*QKVD;
  cudaGetSymbolAddress((void**)&att0, g_att);    att1 = att0 + (size_t)ROWS*CDIM;
  cudaGetSymbolAddress((void**)&lk0,  g_lk);     lk1  = lk0  + (size_t)BHN*NBKT;
  cudaGetSymbolAddress((void**)&lq0,  g_lq);     lq1  = lq0  + (size_t)BHN*NBKT;
  cudaGetSymbolAddress((void**)&lg0,  g_logits); lg1  = lg0  + (size_t)32*NQ*NQ;
  cudaGetSymbolAddress((void**)&ml0,  g_ml);     ml1  = ml0  + (size_t)BHN;
  cudaGetSymbolAddress((void**)&hid0, g_hid);    hid1 = hid0 + (size_t)ROWS*HID;

  const int LOGITS_SMEM = 18688 * 4;
  const int PV_SMEM     = 20064 * 4;
  static int attr_done = 0;
  if (!attr_done){
    cudaFuncSetAttribute(logits_kernel, cudaFuncAttributeMaxDynamicSharedMemorySize, LOGITS_SMEM);
    cudaFuncSetAttribute(pv_kernel,     cudaFuncAttributeMaxDynamicSharedMemorySize, PV_SMEM);
    attr_done = 1;
  }

  // 1. LN
  ln_kernel<<<ROWS, 128>>>(x0, ln00_g, ln00_b, ln0);
  ln_kernel<<<ROWS, 128>>>(x1, ln01_g, ln01_b, ln1);

  // 2. qkv GEMMs
  dim3 gqkv(QKVD/128, ROWS/128);
  sgemm_tf32_kernel<<<gqkv, 256>>>(ln0, w_qkv0, b_qkv0, nullptr, qkv0, ROWS, QKVD, CDIM, 0);
  sgemm_tf32_kernel<<<gqkv, 256>>>(ln1, w_qkv1, b_qkv1, nullptr, qkv1, ROWS, QKVD, CDIM, 0);

  // 3. bias tables
  dim3 gbt(BHN/64, 2, 2);
  biastab_kernel<<<gbt, 256>>>(qkv0, qkv1, table_q, table_k, lk0, lk1, lq0, lq1);

  // 4. logits (both streams)
  dim3 glg(16, 16, 64);
  logits_kernel<<<glg, 256, LOGITS_SMEM>>>(qkv0, qkv1, lk0, lk1, lq0, lq1, lg0, lg1);

  // 5. row max (both streams)
  smax_kernel<<<2*BHN, 256>>>(lg0, ml0);

  // 6. PV + tv table (both streams)
  dim3 gpv(16, 64);
  pv_kernel<<<gpv, 256, PV_SMEM>>>(lg0, lg1, ml0, ml1, qkv0, qkv1, table_v, att0, att1);

  // 7. proj + residual
  dim3 gproj(CDIM/128, ROWS/128);
  sgemm_tf32_kernel<<<gproj, 256>>>(att0, w_proj, b_proj, x0, out0, ROWS, CDIM, CDIM, 0);
  sgemm_tf32_kernel<<<gproj, 256>>>(att1, w_proj, b_proj, x1, out1, ROWS, CDIM, CDIM, 0);

  // 8. MLP
  ln_kernel<<<ROWS, 128>>>(out0, ln10_g, ln10_b, ln0);
  ln_kernel<<<ROWS, 128>>>(out1, ln11_g, ln11_b, ln1);

  dim3 gfc1(HID/128, ROWS/128);
  sgemm_tf32_kernel<<<gfc1, 256>>>(ln0, w_fc1_0, b_fc1_0, nullptr, hid0, ROWS, HID, CDIM, 1);
  sgemm_tf32_kernel<<<gfc1, 256>>>(ln1, w_fc1_1, b_fc1_1, nullptr, hid1, ROWS, HID, CDIM, 1);

  dim3 gfc2(CDIM/128, ROWS/128);
  sgemm_tf32_kernel<<<gfc2, 256>>>(hid0, w_fc2_0, b_fc2_0, out0, out0, ROWS, CDIM, HID, 0);
  sgemm_tf32_kernel<<<gfc2, 256>>>(hid1, w_fc2_1, b_fc2_1, out1, out1, ROWS, CDIM, HID, 0);
}

// round 10
// speedup vs baseline: 1.6165x; 1.0348x over previous
#include <cuda_runtime.h>
#include <cuda_bf16.h>
#include <math.h>
#include <stdint.h>

// ---------------- problem constants ----------------
#define ROWS 4096        // B*N
#define CDIM 512
#define QKVD 1536
#define HID  2048
#define NHEAD 8
#define HD   64
#define NQ   1024
#define BHN  32768       // B*H*N
#define NBKT 81

// ---------------- device scratch ----------------
__device__ float g_ln    [2][ROWS*CDIM];
__device__ float g_qkv   [2][ROWS*QKVD];
__device__ float g_att   [2][ROWS*CDIM];
__device__ float g_lk    [2][(size_t)BHN*NBKT];
__device__ float g_lq    [2][(size_t)BHN*NBKT];
__device__ float g_logits[2][(size_t)32*NQ*NQ];
__device__ float g_ml    [2][BHN];
__device__ float g_hid   [2][(size_t)ROWS*HID];

__constant__ signed char c_pidx[63] = {
  -4,-4,-4,-4,-4,-4,-4,-4,-4,-4,-4,-4,-4,-4,-4,-4,-4,-4,-4,-4,-4,
  -3,-3,-3,-3,-3,-3,-3,
  -2,-2,
  -1,
   0,
   1,
   2, 2,
   3, 3, 3, 3, 3, 3, 3,
   4, 4, 4, 4, 4, 4, 4, 4, 4, 4, 4, 4, 4, 4, 4, 4, 4, 4, 4, 4, 4
};

__device__ __forceinline__ float fexp(float x){
  float y = x * 1.4426950408889634f;
  float n = rintf(y);
  float f = y - n;
  float p =           1.3333558e-3f;
  p = fmaf(p, f, 9.6181291e-3f);
  p = fmaf(p, f, 5.5504108e-2f);
  p = fmaf(p, f, 2.4022650e-1f);
  p = fmaf(p, f, 6.9314718e-1f);
  p = fmaf(p, f, 1.0f);
  int ni = (int)n;
  return p * __int_as_float((ni + 127) << 23);
}

__device__ __forceinline__ uint32_t f2tf32(float v){
  uint32_t r;
  asm("cvt.rna.tf32.f32 %0, %1;" : "=r"(r) : "f"(v));
  return r;
}

__device__ __forceinline__ void mma_tf32(float* c, const uint32_t* a, const uint32_t* b){
  asm volatile(
    "mma.sync.aligned.m16n8k8.row.col.f32.tf32.tf32.f32 "
    "{%0,%1,%2,%3}, {%4,%5,%6,%7}, {%8,%9}, {%0,%1,%2,%3};"
    : "+f"(c[0]), "+f"(c[1]), "+f"(c[2]), "+f"(c[3])
    : "r"(a[0]), "r"(a[1]), "r"(a[2]), "r"(a[3]), "r"(b[0]), "r"(b[1]));
}

__device__ __forceinline__ void cp16(uint32_t dst, const float* src){
  asm volatile("cp.async.cg.shared.global [%0], [%1], 16;\n" :: "r"(dst), "l"(src));
}

__device__ __forceinline__ void atomicMaxF(float* a, float v){
  if (v >= 0.f) atomicMax((int*)a, __float_as_int(v));
  else          atomicMin((unsigned int*)a, __float_as_uint(v));
}

// ---------------- layernorm ------------------------------------------------
__global__ void ln_kernel(const float* __restrict__ x, const float* __restrict__ gam,
                          const float* __restrict__ bet, float* __restrict__ y)
{
  int row = blockIdx.x;
  int t = threadIdx.x;
  const float* xr = x + (size_t)row * CDIM;
  float4 v = *(const float4*)(xr + t*4);
  float s  = v.x + v.y + v.z + v.w;
  float s2 = v.x*v.x + v.y*v.y + v.z*v.z + v.w*v.w;
  #pragma unroll
  for (int o = 16; o > 0; o >>= 1){
    s  += __shfl_xor_sync(0xffffffffu, s , o);
    s2 += __shfl_xor_sync(0xffffffffu, s2, o);
  }
  __shared__ float rs[4], rq[4];
  if ((t & 31) == 0){ rs[t>>5] = s; rq[t>>5] = s2; }
  __syncthreads();
  s  = rs[0]+rs[1]+rs[2]+rs[3];
  s2 = rq[0]+rq[1]+rq[2]+rq[3];
  float mu   = s  * (1.0f/CDIM);
  float var  = s2 * (1.0f/CDIM) - mu*mu;
  float rstd = rsqrtf(var + 1e-5f);
  float4 g4 = *(const float4*)(gam + t*4);
  float4 b4 = *(const float4*)(bet + t*4);
  float4 o4;
  o4.x = (v.x-mu)*rstd*g4.x + b4.x;
  o4.y = (v.y-mu)*rstd*g4.y + b4.y;
  o4.z = (v.z-mu)*rstd*g4.z + b4.z;
  o4.w = (v.w-mu)*rstd*g4.w + b4.w;
  *(float4*)(y + (size_t)row*CDIM + t*4) = o4;
}

// ---------------- ml init (-inf) --------------------------------------------
__global__ void mlinit_kernel(float* __restrict__ ml){
  ml[blockIdx.x*256 + threadIdx.x] = -1e30f;
}

// ---------------- tf32 tensor-core GEMM, cp.async double-buffered ----------
__global__ void __launch_bounds__(256, 2) sgemm_tf32_kernel(
    const float* __restrict__ A, const float* __restrict__ Bm,
    const float* __restrict__ bias, const float* __restrict__ resid,
    float* __restrict__ C, int M, int N, int K, int gelu)
{
  __shared__ float As[2][128*20];
  __shared__ float Bs[2][16*132];
  int t = threadIdx.x;
  int bn = blockIdx.x * 128;
  int bm = blockIdx.y * 128;
  int warp = t >> 5, lane = t & 31;
  int wm = (warp >> 2) << 6;
  int wn = (warp & 3) << 5;
  int g  = lane >> 2;
  int tg = lane & 3;

  float acc[4][4][4];
  #pragma unroll
  for (int mt=0;mt<4;mt++)
    #pragma unroll
    for (int nt=0;nt<4;nt++)
      #pragma unroll
      for (int c=0;c<4;c++) acc[mt][nt][c] = 0.f;

  const float* Ag = A + (size_t)bm * K;
  const float* Bg = Bm + bn;

  uint32_t asb[2], bsb[2];
  asb[0] = (uint32_t)__cvta_generic_to_shared(&As[0][0]);
  asb[1] = (uint32_t)__cvta_generic_to_shared(&As[1][0]);
  bsb[0] = (uint32_t)__cvta_generic_to_shared(&Bs[0][0]);
  bsb[1] = (uint32_t)__cvta_generic_to_shared(&Bs[1][0]);

  int ar[2], as4[2], bkr[2], bnc[2];
  #pragma unroll
  for (int i = 0; i < 2; i++){
    int c = t + (i<<8);
    ar[i]  = c >> 2;  as4[i] = (c & 3) << 2;
    bkr[i] = c >> 5;  bnc[i] = (c & 31) << 2;
  }

  int ntiles = K >> 4;
  #pragma unroll
  for (int i = 0; i < 2; i++){
    cp16(asb[0] + ((ar[i]*20 + as4[i])<<2), Ag + (size_t)ar[i]*K + as4[i]);
    cp16(bsb[0] + ((bkr[i]*132 + bnc[i])<<2), Bg + (size_t)bkr[i]*N + bnc[i]);
  }
  asm volatile("cp.async.commit_group;\n");

  for (int it = 0; it < ntiles; it++){
    int buf = it & 1;
    if (it + 1 < ntiles){
      int k0 = (it+1) << 4;
      int nb = (it+1) & 1;
      #pragma unroll
      for (int i = 0; i < 2; i++){
        cp16(asb[nb] + ((ar[i]*20 + as4[i])<<2), Ag + (size_t)ar[i]*K + k0 + as4[i]);
        cp16(bsb[nb] + ((bkr[i]*132 + bnc[i])<<2), Bg + (size_t)(k0 + bkr[i])*N + bnc[i]);
      }
    }
    asm volatile("cp.async.commit_group;\n");
    asm volatile("cp.async.wait_group 1;\n");
    __syncthreads();

    const float* Ab = As[buf];
    const float* Bb = Bs[buf];
    #pragma unroll
    for (int ks = 0; ks < 16; ks += 8){
      uint32_t af[4][4], bf[4][2];
      #pragma unroll
      for (int mt = 0; mt < 4; mt++){
        int m = wm + (mt<<4) + g;
        af[mt][0] = __float_as_uint(Ab[ m   *20 + ks+tg  ]);
        af[mt][1] = __float_as_uint(Ab[(m+8)*20 + ks+tg  ]);
        af[mt][2] = __float_as_uint(Ab[ m   *20 + ks+tg+4]);
        af[mt][3] = __float_as_uint(Ab[(m+8)*20 + ks+tg+4]);
      }
      #pragma unroll
      for (int nt = 0; nt < 4; nt++){
        int n = wn + (nt<<3) + g;
        bf[nt][0] = __float_as_uint(Bb[(ks+tg  )*132 + n]);
        bf[nt][1] = __float_as_uint(Bb[(ks+tg+4)*132 + n]);
      }
      #pragma unroll
      for (int mt = 0; mt < 4; mt++)
        #pragma unroll
        for (int nt = 0; nt < 4; nt++)
          mma_tf32(acc[mt][nt], af[mt], bf[nt]);
    }
    __syncthreads();
  }

  #pragma unroll
  for (int mt = 0; mt < 4; mt++){
    int row0 = bm + wm + (mt<<4) + g;
    #pragma unroll
    for (int nt = 0; nt < 4; nt++){
      int col = bn + wn + (nt<<3) + (tg<<1);
      float b0 = bias[col], b1 = bias[col+1];
      #pragma unroll
      for (int h = 0; h < 2; h++){
        int row = row0 + (h<<3);
        float r0 = acc[mt][nt][h*2+0] + b0;
        float r1 = acc[mt][nt][h*2+1] + b1;
        if (gelu){
          r0 = 0.5f*r0*(1.0f + erff(r0*0.70710678f));
          r1 = 0.5f*r1*(1.0f + erff(r1*0.70710678f));
        }
        if (resid){
          const float2 rr = *(const float2*)(resid + (size_t)row*N + col);
          r0 += rr.x; r1 += rr.y;
        }
        *(float2*)(C + (size_t)row*N + col) = make_float2(r0, r1);
      }
    }
  }
}

// ---------------- bias tables as tiled GEMM ---------------------------------
__global__ void __launch_bounds__(256) biastab_kernel(
    const float* __restrict__ qkv0, const float* __restrict__ qkv1,
    const float* __restrict__ tq, const float* __restrict__ tk,
    float* __restrict__ lk0, float* __restrict__ lk1,
    float* __restrict__ lq0, float* __restrict__ lq1)
{
  __shared__ float qs[64*65];
  __shared__ float tabT[64*84];

  int t = threadIdx.x;
  int s = blockIdx.z, which = blockIdx.y;
  int base = blockIdx.x << 6;
  const float* src;
  float scl;
  if (which == 0){ src = (s == 0 ? qkv0 : qkv1);       scl = 1.0f;   }
  else           { src = (s == 0 ? qkv1 : qkv0) + 512; scl = 0.125f; }
  const float* tab = (which == 0) ? tk : tq;

  for (int idx = t; idx < NBKT*64; idx += 256){
    int c = idx >> 6, d = idx & 63;
    tabT[d*84 + c] = tab[idx];
  }
  #pragma unroll
  for (int it = 0; it < 4; it++){
    int f = t + (it<<8);
    int r = f >> 4, c4 = (f & 15) << 2;
    int rid = base + r;
    int bh = rid >> 10, n = rid & 1023;
    int b = bh >> 3, h = bh & 7;
    float4 v = *(const float4*)(src + (size_t)((b<<10)+n)*QKVD + (h<<6) + c4);
    qs[r*65+c4+0] = scl*v.x; qs[r*65+c4+1] = scl*v.y;
    qs[r*65+c4+2] = scl*v.z; qs[r*65+c4+3] = scl*v.w;
  }
  __syncthreads();

  int tx = t & 31, ty = t >> 5;
  float acc[8][3];
  #pragma unroll
  for (int i=0;i<8;i++){ acc[i][0]=0.f; acc[i][1]=0.f; acc[i][2]=0.f; }

  #pragma unroll 8
  for (int k = 0; k < 64; k++){
    float b0 = tabT[k*84 + tx];
    float b1 = tabT[k*84 + tx + 32];
    float b2 = (tx < 17) ? tabT[k*84 + tx + 64] : 0.f;
    #pragma unroll
    for (int i = 0; i < 8; i++){
      float a = qs[((ty<<3)+i)*65 + k];
      acc[i][0] = fmaf(a, b0, acc[i][0]);
      acc[i][1] = fmaf(a, b1, acc[i][1]);
      acc[i][2] = fmaf(a, b2, acc[i][2]);
    }
  }

  float* dstbase = (which == 0) ? (s == 0 ? lk0 : lk1) : (s == 0 ? lq0 : lq1);
  #pragma unroll
  for (int i = 0; i < 8; i++){
    int rid = base + (ty<<3) + i;
    float* dst = dstbase + (size_t)rid*NBKT;
    dst[tx]      = acc[i][0];
    dst[tx + 32] = acc[i][1];
    if (tx < 17) dst[tx + 64] = acc[i][2];
  }
}

// ---------------- logits + fused row-max (merged streams) ------------------
__global__ void __launch_bounds__(256) logits_kernel(
    const float* __restrict__ qkv0, const float* __restrict__ qkv1,
    const float* __restrict__ lk0, const float* __restrict__ lk1,
    const float* __restrict__ lq0, const float* __restrict__ lq1,
    float* __restrict__ lg0, float* __restrict__ lg1,
    float* __restrict__ ml0, float* __restrict__ ml1)
{
  extern __shared__ float sm[];
  float* qs  = sm;           // [64][65]
  float* ksm = sm + 4160;    // [64][65]
  float* lks = sm + 8320;    // [64][81]
  float* lqs = sm + 13504;   // [64][81]
  float* rmx = sm + 18688;   // [64][4]

  int t = threadIdx.x;
  int z = blockIdx.z;
  int s = z >> 5;
  int bh = z & 31; int b = bh>>3, h = bh&7;
  int i0 = blockIdx.y<<6, j0 = blockIdx.x<<6;
  size_t rbase = ((size_t)bh)<<10;
  const float* qkv_q  = (s==0) ? qkv0 : qkv1;
  const float* qkv_kv = (s==0) ? qkv1 : qkv0;
  const float* LK     = (s==0) ? lk0  : lk1;
  const float* LQ     = (s==0) ? lq0  : lq1;
  float* S            = (s==0) ? lg0  : lg1;
  float* ML           = (s==0) ? ml0  : ml1;

  const float* qb = qkv_q  + (size_t)(b<<10)*QKVD + (h<<6);
  const float* kb = qkv_kv + (size_t)(b<<10)*QKVD + (h<<6) + 512;
  #pragma unroll
  for (int it = 0; it < 4; it++){
    int f = t + (it<<8);
    int r = f >> 4, c4 = (f & 15) << 2;
    float4 qv = *(const float4*)(qb + (size_t)(i0+r)*QKVD + c4);
    float4 kv = *(const float4*)(kb + (size_t)(j0+r)*QKVD + c4);
    qs[r*65+c4+0]=__uint_as_float(f2tf32(qv.x));
    qs[r*65+c4+1]=__uint_as_float(f2tf32(qv.y));
    qs[r*65+c4+2]=__uint_as_float(f2tf32(qv.z));
    qs[r*65+c4+3]=__uint_as_float(f2tf32(qv.w));
    ksm[r*65+c4+0]=__uint_as_float(f2tf32(kv.x));
    ksm[r*65+c4+1]=__uint_as_float(f2tf32(kv.y));
    ksm[r*65+c4+2]=__uint_as_float(f2tf32(kv.z));
    ksm[r*65+c4+3]=__uint_as_float(f2tf32(kv.w));
  }
  for (int f = t; f < 64*NBKT; f += 256){
    int r = f / NBKT, c = f - r*NBKT;
    lks[f] = LK[(rbase + i0 + r)*NBKT + c];
    lqs[f] = LQ[(rbase + j0 + r)*NBKT + c];
  }
  __syncthreads();

  int warp = t >> 5, lane = t & 31;
  int g = lane >> 2, tg = lane & 3;
  int wm = (warp >> 2) << 5;
  int wn = (warp & 3) << 4;

  float acc[2][2][4];
  #pragma unroll
  for (int mt=0;mt<2;mt++)
    #pragma unroll
    for (int nt=0;nt<2;nt++)
      #pragma unroll
      for (int c=0;c<4;c++) acc[mt][nt][c]=0.f;

  #pragma unroll
  for (int ks = 0; ks < 64; ks += 8){
    uint32_t af[2][4], bf[2][2];
    #pragma unroll
    for (int mt = 0; mt < 2; mt++){
      int r0 = wm + (mt<<4) + g;
      af[mt][0] = __float_as_uint(qs[ r0   *65 + ks+tg  ]);
      af[mt][1] = __float_as_uint(qs[(r0+8)*65 + ks+tg  ]);
      af[mt][2] = __float_as_uint(qs[ r0   *65 + ks+tg+4]);
      af[mt][3] = __float_as_uint(qs[(r0+8)*65 + ks+tg+4]);
    }
    #pragma unroll
    for (int nt = 0; nt < 2; nt++){
      int n = wn + (nt<<3) + g;
      bf[nt][0] = __float_as_uint(ksm[n*65 + ks+tg  ]);
      bf[nt][1] = __float_as_uint(ksm[n*65 + ks+tg+4]);
    }
    #pragma unroll
    for (int mt = 0; mt < 2; mt++)
      #pragma unroll
      for (int nt = 0; nt < 2; nt++)
        mma_tf32(acc[mt][nt], af[mt], bf[nt]);
  }

  float rml[2][2];
  rml[0][0] = rml[0][1] = rml[1][0] = rml[1][1] = -1e30f;

  #pragma unroll
  for (int mt = 0; mt < 2; mt++){
    #pragma unroll
    for (int hh = 0; hh < 2; hh++){
      int il = wm + (mt<<4) + g + (hh<<3);
      int i = i0 + il;
      int yi = i >> 5, xi = i & 31;
      const float* lkrow = lks + il*NBKT;
      #pragma unroll
      for (int nt = 0; nt < 2; nt++){
        int jl = wn + (nt<<3) + (tg<<1);
        int j = j0 + jl;
        int dy0 = yi - (j>>5),     dx0 = xi - (j&31);
        int dy1 = yi - ((j+1)>>5), dx1 = xi - ((j+1)&31);
        int bkt0 = ((int)c_pidx[dy0+31]+4)*9 + ((int)c_pidx[dx0+31]+4);
        int bkt1 = ((int)c_pidx[dy1+31]+4)*9 + ((int)c_pidx[dx1+31]+4);
        float v0 = acc[mt][nt][hh*2+0]*0.125f + lkrow[bkt0] + lqs[jl*NBKT + 80 - bkt0];
        float v1 = acc[mt][nt][hh*2+1]*0.125f + lkrow[bkt1] + lqs[(jl+1)*NBKT + 80 - bkt1];
        *(float2*)(S + (rbase + i)*NQ + j) = make_float2(v0, v1);
        rml[mt][hh] = fmaxf(rml[mt][hh], fmaxf(v0, v1));
      }
    }
  }

  // fused row-max: reduce over tg lanes, then over 4 warp columns, then atomic
  #pragma unroll
  for (int mt = 0; mt < 2; mt++){
    #pragma unroll
    for (int hh = 0; hh < 2; hh++){
      float rm = rml[mt][hh];
      rm = fmaxf(rm, __shfl_xor_sync(0xffffffffu, rm, 1));
      rm = fmaxf(rm, __shfl_xor_sync(0xffffffffu, rm, 2));
      if (tg == 0){
        int il = wm + (mt<<4) + g + (hh<<3);
        rmx[(il<<2) + (warp & 3)] = rm;
      }
    }
  }
  __syncthreads();
  if (t < 64){
    float m = fmaxf(fmaxf(rmx[t<<2], rmx[(t<<2)+1]),
                    fmaxf(rmx[(t<<2)+2], rmx[(t<<2)+3]));
    atomicMaxF(&ML[rbase + i0 + t], m);
  }
}

// ---------------- PV: cp.async double-buffered + scatter + tv-GEMM ---------
// smem floats: s2[2][64*68]=8704 @0, v2[2][64*68]=8704 @8704, sb[64*88] @17408,
//              mrow @23040, rsv @23104 ; tvs overlays v2 region @8704 (88*68)
#define PV_S    0
#define PV_V    8704
#define PV_SB   17408
#define PV_MROW 23040
#define PV_RSV  23104
#define PV_TVS  8704
#define PV_SMEM_FLOATS 23168

__global__ void __launch_bounds__(256) pv_kernel(
    const float* __restrict__ lg0, const float* __restrict__ lg1,
    const float* __restrict__ ml0, const float* __restrict__ ml1,
    const float* __restrict__ qkv0, const float* __restrict__ qkv1,
    const float* __restrict__ tv,
    float* __restrict__ att0, float* __restrict__ att1)
{
  extern __shared__ float sm[];
  float* sb  = sm + PV_SB;
  float* mrow= sm + PV_MROW;
  float* rsv = sm + PV_RSV;

  int t = threadIdx.x;
  int zy = blockIdx.y;
  int s = zy >> 5;
  int bh = zy & 31; int b = bh>>3, h = bh&7;
  int i0 = blockIdx.x << 6;
  size_t rb2 = (((size_t)bh)<<10) + i0;

  const float* S  = (s==0) ? lg0 : lg1;
  const float* ml = (s==0) ? ml0 : ml1;
  const float* qkv_kv = (s==0) ? qkv1 : qkv0;
  float* out = (s==0) ? att0 : att1;

  if (t < 64) mrow[t] = ml[rb2 + t];
  for (int f = t; f < 64*88; f += 256) sb[f] = 0.f;

  const float* vb = qkv_kv + ((size_t)(b<<10))*QKVD + (h<<6) + 1024;

  uint32_t sbs[2], vbs[2];
  sbs[0] = (uint32_t)__cvta_generic_to_shared(sm + PV_S);
  sbs[1] = (uint32_t)__cvta_generic_to_shared(sm + PV_S + 4352);
  vbs[0] = (uint32_t)__cvta_generic_to_shared(sm + PV_V);
  vbs[1] = (uint32_t)__cvta_generic_to_shared(sm + PV_V + 4352);

  // per-thread staging coords: 4 chunks each for S and V
  int cr[4], cc4[4];
  #pragma unroll
  for (int i = 0; i < 4; i++){
    int f = t + (i<<8);
    cr[i] = f >> 4; cc4[i] = (f & 15) << 2;
  }

  // prologue: stage tile 0
  #pragma unroll
  for (int i = 0; i < 4; i++){
    cp16(sbs[0] + ((cr[i]*68 + cc4[i])<<2), S + (rb2 + cr[i])*NQ + cc4[i]);
    cp16(vbs[0] + ((cr[i]*68 + cc4[i])<<2), vb + (size_t)cr[i]*QKVD + cc4[i]);
  }
  asm volatile("cp.async.commit_group;\n");
  __syncthreads();   // covers mrow/sb init too

  int warp = t >> 5, lane = t & 31;
  int g = lane >> 2, tg = lane & 3;
  int wm = (warp >> 2) << 5;
  int wn = (warp & 3) << 4;

  float acc[2][2][4];
  #pragma unroll
  for (int mt=0;mt<2;mt++)
    #pragma unroll
    for (int nt=0;nt<2;nt++)
      #pragma unroll
      for (int c=0;c<4;c++) acc[mt][nt][c]=0.f;

  int sr = t >> 2;
  int q0 = (t & 3) << 4;
  int iglob = i0 + sr;
  int syi = iglob >> 5, sxi = iglob & 31;
  float msr = mrow[sr];

  for (int jt = 0; jt < 16; jt++){
    int buf = jt & 1;
    if (jt + 1 < 16){
      int j0n = (jt+1) << 6;
      int nb = (jt+1) & 1;
      #pragma unroll
      for (int i = 0; i < 4; i++){
        cp16(sbs[nb] + ((cr[i]*68 + cc4[i])<<2), S + (rb2 + cr[i])*NQ + j0n + cc4[i]);
        cp16(vbs[nb] + ((cr[i]*68 + cc4[i])<<2), vb + (size_t)(j0n + cr[i])*QKVD + cc4[i]);
      }
    }
    asm volatile("cp.async.commit_group;\n");
    asm volatile("cp.async.wait_group 1;\n");
    __syncthreads();

    float* ps = sm + PV_S + buf*4352;
    float* vs = sm + PV_V + buf*4352;
    int j0 = jt << 6;

    // exp in place (thread-local rows) + run-length scatter
    {
      float runv = 0.f; int runb = -1;
      #pragma unroll
      for (int q = 0; q < 16; q++){
        int jj = q0 + q;
        int idx = sr*68 + jj;
        float pvv = __uint_as_float(f2tf32(fexp(ps[idx] - msr)));
        ps[idx] = pvv;
        int j = j0 + jj;
        int dy = syi - (j>>5), dx = sxi - (j&31);
        int bkt = ((int)c_pidx[dy+31]+4)*9 + ((int)c_pidx[dx+31]+4);
        if (bkt == runb) runv += pvv;
        else {
          if (runb >= 0) atomicAdd(&sb[sr*88 + runb], runv);
          runb = bkt; runv = pvv;
        }
      }
      atomicAdd(&sb[sr*88 + runb], runv);
    }
    __syncthreads();

    #pragma unroll
    for (int ks = 0; ks < 64; ks += 8){
      uint32_t af[2][4], bf[2][2];
      #pragma unroll
      for (int mt = 0; mt < 2; mt++){
        int r0 = wm + (mt<<4) + g;
        af[mt][0] = __float_as_uint(ps[ r0   *68 + ks+tg  ]);
        af[mt][1] = __float_as_uint(ps[(r0+8)*68 + ks+tg  ]);
        af[mt][2] = __float_as_uint(ps[ r0   *68 + ks+tg+4]);
        af[mt][3] = __float_as_uint(ps[(r0+8)*68 + ks+tg+4]);
      }
      #pragma unroll
      for (int nt = 0; nt < 2; nt++){
        int n = wn + (nt<<3) + g;
        bf[nt][0] = __float_as_uint(vs[(ks+tg  )*68 + n]);
        bf[nt][1] = __float_as_uint(vs[(ks+tg+4)*68 + n]);
      }
      #pragma unroll
      for (int mt = 0; mt < 2; mt++)
        #pragma unroll
        for (int nt = 0; nt < 2; nt++)
          mma_tf32(acc[mt][nt], af[mt], bf[nt]);
    }
    __syncthreads();
  }

  // stage tvs into the (now free) V region: [88][68], zero-padded, tf32
  float* tvs = sm + PV_TVS;
  for (int f = t; f < 88*68; f += 256) tvs[f] = 0.f;
  __syncthreads();
  for (int f = t; f < NBKT*64; f += 256){
    int c = f >> 6, d = f & 63;
    tvs[c*68 + d] = __uint_as_float(f2tf32(tv[f]));
  }
  if (t < 64){
    float ssum = 0.f;
    #pragma unroll
    for (int c = 0; c < NBKT; c++) ssum += sb[t*88 + c];
    rsv[t] = 1.0f / ssum;
  }
  __syncthreads();

  #pragma unroll
  for (int ks = 0; ks < 88; ks += 8){
    uint32_t af[2][4], bf[2][2];
    #pragma unroll
    for (int mt = 0; mt < 2; mt++){
      int r0 = wm + (mt<<4) + g;
      af[mt][0] = __float_as_uint(sb[ r0   *88 + ks+tg  ]);
      af[mt][1] = __float_as_uint(sb[(r0+8)*88 + ks+tg  ]);
      af[mt][2] = __float_as_uint(sb[ r0   *88 + ks+tg+4]);
      af[mt][3] = __float_as_uint(sb[(r0+8)*88 + ks+tg+4]);
    }
    #pragma unroll
    for (int nt = 0; nt < 2; nt++){
      int n = wn + (nt<<3) + g;
      bf[nt][0] = __float_as_uint(tvs[(ks+tg  )*68 + n]);
      bf[nt][1] = __float_as_uint(tvs[(ks+tg+4)*68 + n]);
    }
    #pragma unroll
    for (int mt = 0; mt < 2; mt++)
      #pragma unroll
      for (int nt = 0; nt < 2; nt++)
        mma_tf32(acc[mt][nt], af[mt], bf[nt]);
  }

  #pragma unroll
  for (int mt = 0; mt < 2; mt++){
    #pragma unroll
    for (int hh = 0; hh < 2; hh++){
      int r = wm + (mt<<4) + g + (hh<<3);
      float inv = rsv[r];
      #pragma unroll
      for (int nt = 0; nt < 2; nt++){
        int col = wn + (nt<<3) + (tg<<1);
        float o0 = acc[mt][nt][hh*2+0] * inv;
        float o1 = acc[mt][nt][hh*2+1] * inv;
        float* op = out + ((size_t)(b<<10) + i0 + r)*CDIM + (h<<6) + col;
        *(float2*)op = make_float2(o0, o1);
      }
    }
  }
}

// ---------------- launch ----------------------------------------------------
extern "C" void kernel_launch(void* const* d_in, const int* in_sizes, int n_in,
                              void* d_out, int out_size)
{
  const float* x0     = (const float*)d_in[0];
  const float* x1     = (const float*)d_in[1];
  const float* ln00_g = (const float*)d_in[2];
  const float* ln00_b = (const float*)d_in[3];
  const float* ln01_g = (const float*)d_in[4];
  const float* ln01_b = (const float*)d_in[5];
  const float* ln10_g = (const float*)d_in[6];
  const float* ln10_b = (const float*)d_in[7];
  const float* ln11_g = (const float*)d_in[8];
  const float* ln11_b = (const float*)d_in[9];
  const float* w_qkv0 = (const float*)d_in[10];
  const float* b_qkv0 = (const float*)d_in[11];
  const float* w_qkv1 = (const float*)d_in[12];
  const float* b_qkv1 = (const float*)d_in[13];
  const float* w_proj = (const float*)d_in[14];
  const float* b_proj = (const float*)d_in[15];
  const float* table_q= (const float*)d_in[16];
  const float* table_k= (const float*)d_in[17];
  const float* table_v= (const float*)d_in[18];
  const float* w_fc1_0= (const float*)d_in[19];
  const float* b_fc1_0= (const float*)d_in[20];
  const float* w_fc2_0= (const float*)d_in[21];
  const float* b_fc2_0= (const float*)d_in[22];
  const float* w_fc1_1= (const float*)d_in[23];
  const float* b_fc1_1= (const float*)d_in[24];
  const float* w_fc2_1= (const float*)d_in[25];
  const float* b_fc2_1= (const float*)d_in[26];

  float* out0 = (float*)d_out;
  float* out1 = (float*)d_out + (size_t)ROWS*CDIM;

  float *ln0, *ln1, *qkv0, *qkv1, *att0, *att1, *lk0, *lk1, *lq0, *lq1;
  float *lg0, *lg1, *ml0, *ml1, *hid0, *hid1;
  cudaGetSymbolAddress((void**)&ln0,  g_ln);     ln1  = ln0  + (size_t)ROWS*CDIM;
  cudaGetSymbolAddress((void**)&qkv0, g_qkv);    qkv1 = qkv0 + (size_t)ROWS*QKVD;
  cudaGetSymbolAddress((void**)&att0, g_att);    att1 = att0 + (size_t)ROWS*CDIM;
  cudaGetSymbolAddress((void**)&lk0,  g_lk);     lk1  = lk0  + (size_t)BHN*NBKT;
  cudaGetSymbolAddress((void**)&lq0,  g_lq);     lq1  = lq0  + (size_t)BHN*NBKT;
  cudaGetSymbolAddress((void**)&lg0,  g_logits); lg1  = lg0  + (size_t)32*NQ*NQ;
  cudaGetSymbolAddress((void**)&ml0,  g_ml);     ml1  = ml0  + (size_t)BHN;
  cudaGetSymbolAddress((void**)&hid0, g_hid);    hid1 = hid0 + (size_t)ROWS*HID;

  const int LOGITS_SMEM = 18944 * 4;   // +rmx
  const int PV_SMEM     = PV_SMEM_FLOATS * 4;  // 92672 B
  static int attr_done = 0;
  if (!attr_done){
    cudaFuncSetAttribute(logits_kernel, cudaFuncAttributeMaxDynamicSharedMemorySize, LOGITS_SMEM);
    cudaFuncSetAttribute(pv_kernel,     cudaFuncAttributeMaxDynamicSharedMemorySize, PV_SMEM);
    attr_done = 1;
  }

  // 1. LN + ml init
  ln_kernel<<<ROWS, 128>>>(x0, ln00_g, ln00_b, ln0);
  ln_kernel<<<ROWS, 128>>>(x1, ln01_g, ln01_b, ln1);
  mlinit_kernel<<<(2*BHN)/256, 256>>>(ml0);

  // 2. qkv GEMMs
  dim3 gqkv(QKVD/128, ROWS/128);
  sgemm_tf32_kernel<<<gqkv, 256>>>(ln0, w_qkv0, b_qkv0, nullptr, qkv0, ROWS, QKVD, CDIM, 0);
  sgemm_tf32_kernel<<<gqkv, 256>>>(ln1, w_qkv1, b_qkv1, nullptr, qkv1, ROWS, QKVD, CDIM, 0);

  // 3. bias tables
  dim3 gbt(BHN/64, 2, 2);
  biastab_kernel<<<gbt, 256>>>(qkv0, qkv1, table_q, table_k, lk0, lk1, lq0, lq1);

  // 4. logits + fused row max (both streams)
  dim3 glg(16, 16, 64);
  logits_kernel<<<glg, 256, LOGITS_SMEM>>>(qkv0, qkv1, lk0, lk1, lq0, lq1,
                                           lg0, lg1, ml0, ml1);

  // 5. PV + tv table (both streams)
  dim3 gpv(16, 64);
  pv_kernel<<<gpv, 256, PV_SMEM>>>(lg0, lg1, ml0, ml1, qkv0, qkv1, table_v, att0, att1);

  // 6. proj + residual
  dim3 gproj(CDIM/128, ROWS/128);
  sgemm_tf32_kernel<<<gproj, 256>>>(att0, w_proj, b_proj, x0, out0, ROWS, CDIM, CDIM, 0);
  sgemm_tf32_kernel<<<gproj, 256>>>(att1, w_proj, b_proj, x1, out1, ROWS, CDIM, CDIM, 0);

  // 7. MLP
  ln_kernel<<<ROWS, 128>>>(out0, ln10_g, ln10_b, ln0);
  ln_kernel<<<ROWS, 128>>>(out1, ln11_g, ln11_b, ln1);

  dim3 gfc1(HID/128, ROWS/128);
  sgemm_tf32_kernel<<<gfc1, 256>>>(ln0, w_fc1_0, b_fc1_0, nullptr, hid0, ROWS, HID, CDIM, 1);
  sgemm_tf32_kernel<<<gfc1, 256>>>(ln1, w_fc1_1, b_fc1_1, nullptr, hid1, ROWS, HID, CDIM, 1);

  dim3 gfc2(CDIM/128, ROWS/128);
  sgemm_tf32_kernel<<<gfc2, 256>>>(hid0, w_fc2_0, b_fc2_0, out0, out0, ROWS, CDIM, HID, 0);
  sgemm_tf32_kernel<<<gfc2, 256>>>(hid1, w_fc2_1, b_fc2_1, out1, out1, ROWS, CDIM, HID, 0);
}

// round 13
// speedup vs baseline: 1.6226x; 1.0038x over previous
#include <cuda_runtime.h>
#include <cuda_bf16.h>
#include <math.h>
#include <stdint.h>

// ---------------- problem constants ----------------
#define ROWS 4096        // B*N
#define CDIM 512
#define QKVD 1536
#define HID  2048
#define NHEAD 8
#define HD   64
#define NQ   1024
#define BHN  32768       // B*H*N
#define NBKT 81

// ---------------- device scratch ----------------
__device__ float g_ln    [2][ROWS*CDIM];
__device__ float g_qkv   [2][ROWS*QKVD];
__device__ float g_att   [2][ROWS*CDIM];
__device__ float g_lk    [2][(size_t)BHN*NBKT];
__device__ float g_lq    [2][(size_t)BHN*NBKT];
__device__ float g_logits[2][(size_t)32*NQ*NQ];
__device__ float g_ml    [2][BHN];
__device__ float g_hid   [2][(size_t)ROWS*HID];

__constant__ signed char c_pidx[63] = {
  -4,-4,-4,-4,-4,-4,-4,-4,-4,-4,-4,-4,-4,-4,-4,-4,-4,-4,-4,-4,-4,
  -3,-3,-3,-3,-3,-3,-3,
  -2,-2,
  -1,
   0,
   1,
   2, 2,
   3, 3, 3, 3, 3, 3, 3,
   4, 4, 4, 4, 4, 4, 4, 4, 4, 4, 4, 4, 4, 4, 4, 4, 4, 4, 4, 4, 4
};

__device__ __forceinline__ float fexp(float x){
  float y = x * 1.4426950408889634f;
  float n = rintf(y);
  float f = y - n;
  float p =           1.3333558e-3f;
  p = fmaf(p, f, 9.6181291e-3f);
  p = fmaf(p, f, 5.5504108e-2f);
  p = fmaf(p, f, 2.4022650e-1f);
  p = fmaf(p, f, 6.9314718e-1f);
  p = fmaf(p, f, 1.0f);
  int ni = (int)n;
  return p * __int_as_float((ni + 127) << 23);
}

__device__ __forceinline__ uint32_t f2tf32(float v){
  uint32_t r;
  asm("cvt.rna.tf32.f32 %0, %1;" : "=r"(r) : "f"(v));
  return r;
}

__device__ __forceinline__ void mma_tf32(float* c, const uint32_t* a, const uint32_t* b){
  asm volatile(
    "mma.sync.aligned.m16n8k8.row.col.f32.tf32.tf32.f32 "
    "{%0,%1,%2,%3}, {%4,%5,%6,%7}, {%8,%9}, {%0,%1,%2,%3};"
    : "+f"(c[0]), "+f"(c[1]), "+f"(c[2]), "+f"(c[3])
    : "r"(a[0]), "r"(a[1]), "r"(a[2]), "r"(a[3]), "r"(b[0]), "r"(b[1]));
}

__device__ __forceinline__ void cp16(uint32_t dst, const float* src){
  asm volatile("cp.async.cg.shared.global [%0], [%1], 16;\n" :: "r"(dst), "l"(src));
}

__device__ __forceinline__ void atomicMaxF(float* a, float v){
  if (v >= 0.f) atomicMax((int*)a, __float_as_int(v));
  else          atomicMin((unsigned int*)a, __float_as_uint(v));
}

struct GemmPtrs {
  const float* A[2];
  const float* B[2];
  const float* bias[2];
  const float* resid[2];
  float* C[2];
};

// ---------------- layernorm (paired streams via blockIdx.y) -----------------
__global__ void ln_kernel(const float* __restrict__ x0, const float* __restrict__ x1,
                          const float* __restrict__ g0, const float* __restrict__ g1,
                          const float* __restrict__ be0, const float* __restrict__ be1,
                          float* __restrict__ y0, float* __restrict__ y1)
{
  int sIdx = blockIdx.y;
  const float* x  = sIdx ? x1 : x0;
  const float* gam= sIdx ? g1 : g0;
  const float* bet= sIdx ? be1 : be0;
  float* y        = sIdx ? y1 : y0;
  int row = blockIdx.x;
  int t = threadIdx.x;
  const float* xr = x + (size_t)row * CDIM;
  float4 v = *(const float4*)(xr + t*4);
  float s  = v.x + v.y + v.z + v.w;
  float s2 = v.x*v.x + v.y*v.y + v.z*v.z + v.w*v.w;
  #pragma unroll
  for (int o = 16; o > 0; o >>= 1){
    s  += __shfl_xor_sync(0xffffffffu, s , o);
    s2 += __shfl_xor_sync(0xffffffffu, s2, o);
  }
  __shared__ float rs[4], rq[4];
  if ((t & 31) == 0){ rs[t>>5] = s; rq[t>>5] = s2; }
  __syncthreads();
  s  = rs[0]+rs[1]+rs[2]+rs[3];
  s2 = rq[0]+rq[1]+rq[2]+rq[3];
  float mu   = s  * (1.0f/CDIM);
  float var  = s2 * (1.0f/CDIM) - mu*mu;
  float rstd = rsqrtf(var + 1e-5f);
  float4 g4 = *(const float4*)(gam + t*4);
  float4 b4 = *(const float4*)(bet + t*4);
  float4 o4;
  o4.x = (v.x-mu)*rstd*g4.x + b4.x;
  o4.y = (v.y-mu)*rstd*g4.y + b4.y;
  o4.z = (v.z-mu)*rstd*g4.z + b4.z;
  o4.w = (v.w-mu)*rstd*g4.w + b4.w;
  *(float4*)(y + (size_t)row*CDIM + t*4) = o4;
}

// ---------------- ml init (-inf) --------------------------------------------
__global__ void mlinit_kernel(float* __restrict__ ml){
  ml[blockIdx.x*256 + threadIdx.x] = -1e30f;
}

// ---------------- tf32 GEMM, cp.async double-buffered, BN templated --------
// BN=128: 8 warps 2x4, warp 64x32.  BN=64: 8 warps 4x2, warp 32x32.
template <int BN>
__global__ void __launch_bounds__(256, 2) sgemm_tf32_kernel(
    GemmPtrs p, int M, int N, int K, int gelu)
{
  constexpr int BSTR = BN + 4;
  constexpr int MT = (BN == 128) ? 4 : 2;
  constexpr int NT = 4;
  constexpr int NBCH = (BN == 128) ? 2 : 1;
  __shared__ float As[2][128*20];
  __shared__ float Bs[2][16*BSTR];
  int t = threadIdx.x;
  int z = blockIdx.z;
  const float* A     = p.A[z];
  const float* Bm    = p.B[z];
  const float* bias  = p.bias[z];
  const float* resid = p.resid[z];
  float* C           = p.C[z];

  int bn = blockIdx.x * BN;
  int bm = blockIdx.y * 128;
  int warp = t >> 5, lane = t & 31;
  int wm, wn;
  if (BN == 128){ wm = (warp >> 2) << 6; wn = (warp & 3) << 5; }
  else          { wm = (warp >> 1) << 5; wn = (warp & 1) << 5; }
  int g  = lane >> 2;
  int tg = lane & 3;

  float acc[MT][NT][4];
  #pragma unroll
  for (int mt=0;mt<MT;mt++)
    #pragma unroll
    for (int nt=0;nt<NT;nt++)
      #pragma unroll
      for (int c=0;c<4;c++) acc[mt][nt][c] = 0.f;

  const float* Ag = A + (size_t)bm * K;
  const float* Bg = Bm + bn;

  uint32_t asb[2], bsb[2];
  asb[0] = (uint32_t)__cvta_generic_to_shared(&As[0][0]);
  asb[1] = (uint32_t)__cvta_generic_to_shared(&As[1][0]);
  bsb[0] = (uint32_t)__cvta_generic_to_shared(&Bs[0][0]);
  bsb[1] = (uint32_t)__cvta_generic_to_shared(&Bs[1][0]);

  int ar[2], as4[2], bkr[NBCH], bnc[NBCH];
  #pragma unroll
  for (int i = 0; i < 2; i++){
    int c = t + (i<<8);
    ar[i]  = c >> 2;  as4[i] = (c & 3) << 2;
  }
  #pragma unroll
  for (int i = 0; i < NBCH; i++){
    int c = t + (i<<8);
    if (BN == 128){ bkr[i] = c >> 5; bnc[i] = (c & 31) << 2; }
    else          { bkr[i] = c >> 4; bnc[i] = (c & 15) << 2; }
  }

  int ntiles = K >> 4;
  #pragma unroll
  for (int i = 0; i < 2; i++)
    cp16(asb[0] + ((ar[i]*20 + as4[i])<<2), Ag + (size_t)ar[i]*K + as4[i]);
  #pragma unroll
  for (int i = 0; i < NBCH; i++)
    cp16(bsb[0] + ((bkr[i]*BSTR + bnc[i])<<2), Bg + (size_t)bkr[i]*N + bnc[i]);
  asm volatile("cp.async.commit_group;\n");

  for (int it = 0; it < ntiles; it++){
    int buf = it & 1;
    if (it + 1 < ntiles){
      int k0 = (it+1) << 4;
      int nb = (it+1) & 1;
      #pragma unroll
      for (int i = 0; i < 2; i++)
        cp16(asb[nb] + ((ar[i]*20 + as4[i])<<2), Ag + (size_t)ar[i]*K + k0 + as4[i]);
      #pragma unroll
      for (int i = 0; i < NBCH; i++)
        cp16(bsb[nb] + ((bkr[i]*BSTR + bnc[i])<<2), Bg + (size_t)(k0 + bkr[i])*N + bnc[i]);
    }
    asm volatile("cp.async.commit_group;\n");
    asm volatile("cp.async.wait_group 1;\n");
    __syncthreads();

    const float* Ab = As[buf];
    const float* Bb = Bs[buf];
    #pragma unroll
    for (int ks = 0; ks < 16; ks += 8){
      uint32_t af[MT][4], bf[NT][2];
      #pragma unroll
      for (int mt = 0; mt < MT; mt++){
        int m = wm + (mt<<4) + g;
        af[mt][0] = __float_as_uint(Ab[ m   *20 + ks+tg  ]);
        af[mt][1] = __float_as_uint(Ab[(m+8)*20 + ks+tg  ]);
        af[mt][2] = __float_as_uint(Ab[ m   *20 + ks+tg+4]);
        af[mt][3] = __float_as_uint(Ab[(m+8)*20 + ks+tg+4]);
      }
      #pragma unroll
      for (int nt = 0; nt < NT; nt++){
        int n = wn + (nt<<3) + g;
        bf[nt][0] = __float_as_uint(Bb[(ks+tg  )*BSTR + n]);
        bf[nt][1] = __float_as_uint(Bb[(ks+tg+4)*BSTR + n]);
      }
      #pragma unroll
      for (int mt = 0; mt < MT; mt++)
        #pragma unroll
        for (int nt = 0; nt < NT; nt++)
          mma_tf32(acc[mt][nt], af[mt], bf[nt]);
    }
    __syncthreads();
  }

  #pragma unroll
  for (int mt = 0; mt < MT; mt++){
    int row0 = bm + wm + (mt<<4) + g;
    #pragma unroll
    for (int nt = 0; nt < NT; nt++){
      int col = bn + wn + (nt<<3) + (tg<<1);
      float b0 = bias[col], b1 = bias[col+1];
      #pragma unroll
      for (int h = 0; h < 2; h++){
        int row = row0 + (h<<3);
        float r0 = acc[mt][nt][h*2+0] + b0;
        float r1 = acc[mt][nt][h*2+1] + b1;
        if (gelu){
          r0 = 0.5f*r0*(1.0f + erff(r0*0.70710678f));
          r1 = 0.5f*r1*(1.0f + erff(r1*0.70710678f));
        }
        if (resid){
          const float2 rr = *(const float2*)(resid + (size_t)row*N + col);
          r0 += rr.x; r1 += rr.y;
        }
        *(float2*)(C + (size_t)row*N + col) = make_float2(r0, r1);
      }
    }
  }
}

// ---------------- bias tables as tiled GEMM ---------------------------------
__global__ void __launch_bounds__(256) biastab_kernel(
    const float* __restrict__ qkv0, const float* __restrict__ qkv1,
    const float* __restrict__ tq, const float* __restrict__ tk,
    float* __restrict__ lk0, float* __restrict__ lk1,
    float* __restrict__ lq0, float* __restrict__ lq1)
{
  __shared__ float qs[64*65];
  __shared__ float tabT[64*84];

  int t = threadIdx.x;
  int s = blockIdx.z, which = blockIdx.y;
  int base = blockIdx.x << 6;
  const float* src;
  float scl;
  if (which == 0){ src = (s == 0 ? qkv0 : qkv1);       scl = 1.0f;   }
  else           { src = (s == 0 ? qkv1 : qkv0) + 512; scl = 0.125f; }
  const float* tab = (which == 0) ? tk : tq;

  for (int idx = t; idx < NBKT*64; idx += 256){
    int c = idx >> 6, d = idx & 63;
    tabT[d*84 + c] = tab[idx];
  }
  #pragma unroll
  for (int it = 0; it < 4; it++){
    int f = t + (it<<8);
    int r = f >> 4, c4 = (f & 15) << 2;
    int rid = base + r;
    int bh = rid >> 10, n = rid & 1023;
    int b = bh >> 3, h = bh & 7;
    float4 v = *(const float4*)(src + (size_t)((b<<10)+n)*QKVD + (h<<6) + c4);
    qs[r*65+c4+0] = scl*v.x; qs[r*65+c4+1] = scl*v.y;
    qs[r*65+c4+2] = scl*v.z; qs[r*65+c4+3] = scl*v.w;
  }
  __syncthreads();

  int tx = t & 31, ty = t >> 5;
  float acc[8][3];
  #pragma unroll
  for (int i=0;i<8;i++){ acc[i][0]=0.f; acc[i][1]=0.f; acc[i][2]=0.f; }

  #pragma unroll 8
  for (int k = 0; k < 64; k++){
    float b0 = tabT[k*84 + tx];
    float b1 = tabT[k*84 + tx + 32];
    float b2 = (tx < 17) ? tabT[k*84 + tx + 64] : 0.f;
    #pragma unroll
    for (int i = 0; i < 8; i++){
      float a = qs[((ty<<3)+i)*65 + k];
      acc[i][0] = fmaf(a, b0, acc[i][0]);
      acc[i][1] = fmaf(a, b1, acc[i][1]);
      acc[i][2] = fmaf(a, b2, acc[i][2]);
    }
  }

  float* dstbase = (which == 0) ? (s == 0 ? lk0 : lk1) : (s == 0 ? lq0 : lq1);
  #pragma unroll
  for (int i = 0; i < 8; i++){
    int rid = base + (ty<<3) + i;
    float* dst = dstbase + (size_t)rid*NBKT;
    dst[tx]      = acc[i][0];
    dst[tx + 32] = acc[i][1];
    if (tx < 17) dst[tx + 64] = acc[i][2];
  }
}

// ---------------- logits + fused row-max (merged streams) ------------------
__global__ void __launch_bounds__(256) logits_kernel(
    const float* __restrict__ qkv0, const float* __restrict__ qkv1,
    const float* __restrict__ lk0, const float* __restrict__ lk1,
    const float* __restrict__ lq0, const float* __restrict__ lq1,
    float* __restrict__ lg0, float* __restrict__ lg1,
    float* __restrict__ ml0, float* __restrict__ ml1)
{
  extern __shared__ float sm[];
  float* qs  = sm;           // [64][65]
  float* ksm = sm + 4160;    // [64][65]
  float* lks = sm + 8320;    // [64][81]
  float* lqs = sm + 13504;   // [64][81]
  float* rmx = sm + 18688;   // [64][4]

  int t = threadIdx.x;
  int z = blockIdx.z;
  int s = z >> 5;
  int bh = z & 31; int b = bh>>3, h = bh&7;
  int i0 = blockIdx.y<<6, j0 = blockIdx.x<<6;
  size_t rbase = ((size_t)bh)<<10;
  const float* qkv_q  = (s==0) ? qkv0 : qkv1;
  const float* qkv_kv = (s==0) ? qkv1 : qkv0;
  const float* LK     = (s==0) ? lk0  : lk1;
  const float* LQ     = (s==0) ? lq0  : lq1;
  float* S            = (s==0) ? lg0  : lg1;
  float* ML           = (s==0) ? ml0  : ml1;

  const float* qb = qkv_q  + (size_t)(b<<10)*QKVD + (h<<6);
  const float* kb = qkv_kv + (size_t)(b<<10)*QKVD + (h<<6) + 512;
  #pragma unroll
  for (int it = 0; it < 4; it++){
    int f = t + (it<<8);
    int r = f >> 4, c4 = (f & 15) << 2;
    float4 qv = *(const float4*)(qb + (size_t)(i0+r)*QKVD + c4);
    float4 kv = *(const float4*)(kb + (size_t)(j0+r)*QKVD + c4);
    qs[r*65+c4+0]=__uint_as_float(f2tf32(qv.x));
    qs[r*65+c4+1]=__uint_as_float(f2tf32(qv.y));
    qs[r*65+c4+2]=__uint_as_float(f2tf32(qv.z));
    qs[r*65+c4+3]=__uint_as_float(f2tf32(qv.w));
    ksm[r*65+c4+0]=__uint_as_float(f2tf32(kv.x));
    ksm[r*65+c4+1]=__uint_as_float(f2tf32(kv.y));
    ksm[r*65+c4+2]=__uint_as_float(f2tf32(kv.z));
    ksm[r*65+c4+3]=__uint_as_float(f2tf32(kv.w));
  }
  for (int f = t; f < 64*NBKT; f += 256){
    int r = f / NBKT, c = f - r*NBKT;
    lks[f] = LK[(rbase + i0 + r)*NBKT + c];
    lqs[f] = LQ[(rbase + j0 + r)*NBKT + c];
  }
  __syncthreads();

  int warp = t >> 5, lane = t & 31;
  int g = lane >> 2, tg = lane & 3;
  int wm = (warp >> 2) << 5;
  int wn = (warp & 3) << 4;

  float acc[2][2][4];
  #pragma unroll
  for (int mt=0;mt<2;mt++)
    #pragma unroll
    for (int nt=0;nt<2;nt++)
      #pragma unroll
      for (int c=0;c<4;c++) acc[mt][nt][c]=0.f;

  #pragma unroll
  for (int ks = 0; ks < 64; ks += 8){
    uint32_t af[2][4], bf[2][2];
    #pragma unroll
    for (int mt = 0; mt < 2; mt++){
      int r0 = wm + (mt<<4) + g;
      af[mt][0] = __float_as_uint(qs[ r0   *65 + ks+tg  ]);
      af[mt][1] = __float_as_uint(qs[(r0+8)*65 + ks+tg  ]);
      af[mt][2] = __float_as_uint(qs[ r0   *65 + ks+tg+4]);
      af[mt][3] = __float_as_uint(qs[(r0+8)*65 + ks+tg+4]);
    }
    #pragma unroll
    for (int nt = 0; nt < 2; nt++){
      int n = wn + (nt<<3) + g;
      bf[nt][0] = __float_as_uint(ksm[n*65 + ks+tg  ]);
      bf[nt][1] = __float_as_uint(ksm[n*65 + ks+tg+4]);
    }
    #pragma unroll
    for (int mt = 0; mt < 2; mt++)
      #pragma unroll
      for (int nt = 0; nt < 2; nt++)
        mma_tf32(acc[mt][nt], af[mt], bf[nt]);
  }

  float rml[2][2];
  rml[0][0] = rml[0][1] = rml[1][0] = rml[1][1] = -1e30f;

  #pragma unroll
  for (int mt = 0; mt < 2; mt++){
    #pragma unroll
    for (int hh = 0; hh < 2; hh++){
      int il = wm + (mt<<4) + g + (hh<<3);
      int i = i0 + il;
      int yi = i >> 5, xi = i & 31;
      const float* lkrow = lks + il*NBKT;
      #pragma unroll
      for (int nt = 0; nt < 2; nt++){
        int jl = wn + (nt<<3) + (tg<<1);
        int j = j0 + jl;
        int dy0 = yi - (j>>5),     dx0 = xi - (j&31);
        int dy1 = yi - ((j+1)>>5), dx1 = xi - ((j+1)&31);
        int bkt0 = ((int)c_pidx[dy0+31]+4)*9 + ((int)c_pidx[dx0+31]+4);
        int bkt1 = ((int)c_pidx[dy1+31]+4)*9 + ((int)c_pidx[dx1+31]+4);
        float v0 = acc[mt][nt][hh*2+0]*0.125f + lkrow[bkt0] + lqs[jl*NBKT + 80 - bkt0];
        float v1 = acc[mt][nt][hh*2+1]*0.125f + lkrow[bkt1] + lqs[(jl+1)*NBKT + 80 - bkt1];
        *(float2*)(S + (rbase + i)*NQ + j) = make_float2(v0, v1);
        rml[mt][hh] = fmaxf(rml[mt][hh], fmaxf(v0, v1));
      }
    }
  }

  #pragma unroll
  for (int mt = 0; mt < 2; mt++){
    #pragma unroll
    for (int hh = 0; hh < 2; hh++){
      float rm = rml[mt][hh];
      rm = fmaxf(rm, __shfl_xor_sync(0xffffffffu, rm, 1));
      rm = fmaxf(rm, __shfl_xor_sync(0xffffffffu, rm, 2));
      if (tg == 0){
        int il = wm + (mt<<4) + g + (hh<<3);
        rmx[(il<<2) + (warp & 3)] = rm;
      }
    }
  }
  __syncthreads();
  if (t < 64){
    float m = fmaxf(fmaxf(rmx[t<<2], rmx[(t<<2)+1]),
                    fmaxf(rmx[(t<<2)+2], rmx[(t<<2)+3]));
    atomicMaxF(&ML[rbase + i0 + t], m);
  }
}

// ---------------- PV: cp.async double-buffered + scatter + tv-GEMM ---------
#define PV_S    0
#define PV_V    8704
#define PV_SB   17408
#define PV_MROW 23040
#define PV_RSV  23104
#define PV_TVS  8704
#define PV_SMEM_FLOATS 23168

__global__ void __launch_bounds__(256) pv_kernel(
    const float* __restrict__ lg0, const float* __restrict__ lg1,
    const float* __restrict__ ml0, const float* __restrict__ ml1,
    const float* __restrict__ qkv0, const float* __restrict__ qkv1,
    const float* __restrict__ tv,
    float* __restrict__ att0, float* __restrict__ att1)
{
  extern __shared__ float sm[];
  float* sb  = sm + PV_SB;
  float* mrow= sm + PV_MROW;
  float* rsv = sm + PV_RSV;

  int t = threadIdx.x;
  int zy = blockIdx.y;
  int s = zy >> 5;
  int bh = zy & 31; int b = bh>>3, h = bh&7;
  int i0 = blockIdx.x << 6;
  size_t rb2 = (((size_t)bh)<<10) + i0;

  const float* S  = (s==0) ? lg0 : lg1;
  const float* ml = (s==0) ? ml0 : ml1;
  const float* qkv_kv = (s==0) ? qkv1 : qkv0;
  float* out = (s==0) ? att0 : att1;

  if (t < 64) mrow[t] = ml[rb2 + t];
  for (int f = t; f < 64*88; f += 256) sb[f] = 0.f;

  const float* vb = qkv_kv + ((size_t)(b<<10))*QKVD + (h<<6) + 1024;

  uint32_t sbs[2], vbs[2];
  sbs[0] = (uint32_t)__cvta_generic_to_shared(sm + PV_S);
  sbs[1] = (uint32_t)__cvta_generic_to_shared(sm + PV_S + 4352);
  vbs[0] = (uint32_t)__cvta_generic_to_shared(sm + PV_V);
  vbs[1] = (uint32_t)__cvta_generic_to_shared(sm + PV_V + 4352);

  int cr[4], cc4[4];
  #pragma unroll
  for (int i = 0; i < 4; i++){
    int f = t + (i<<8);
    cr[i] = f >> 4; cc4[i] = (f & 15) << 2;
  }

  #pragma unroll
  for (int i = 0; i < 4; i++){
    cp16(sbs[0] + ((cr[i]*68 + cc4[i])<<2), S + (rb2 + cr[i])*NQ + cc4[i]);
    cp16(vbs[0] + ((cr[i]*68 + cc4[i])<<2), vb + (size_t)cr[i]*QKVD + cc4[i]);
  }
  asm volatile("cp.async.commit_group;\n");
  __syncthreads();

  int warp = t >> 5, lane = t & 31;
  int g = lane >> 2, tg = lane & 3;
  int wm = (warp >> 2) << 5;
  int wn = (warp & 3) << 4;

  float acc[2][2][4];
  #pragma unroll
  for (int mt=0;mt<2;mt++)
    #pragma unroll
    for (int nt=0;nt<2;nt++)
      #pragma unroll
      for (int c=0;c<4;c++) acc[mt][nt][c]=0.f;

  int sr = t >> 2;
  int q0 = (t & 3) << 4;
  int iglob = i0 + sr;
  int syi = iglob >> 5, sxi = iglob & 31;
  float msr = mrow[sr];

  for (int jt = 0; jt < 16; jt++){
    int buf = jt & 1;
    if (jt + 1 < 16){
      int j0n = (jt+1) << 6;
      int nb = (jt+1) & 1;
      #pragma unroll
      for (int i = 0; i < 4; i++){
        cp16(sbs[nb] + ((cr[i]*68 + cc4[i])<<2), S + (rb2 + cr[i])*NQ + j0n + cc4[i]);
        cp16(vbs[nb] + ((cr[i]*68 + cc4[i])<<2), vb + (size_t)(j0n + cr[i])*QKVD + cc4[i]);
      }
    }
    asm volatile("cp.async.commit_group;\n");
    asm volatile("cp.async.wait_group 1;\n");
    __syncthreads();

    float* ps = sm + PV_S + buf*4352;
    float* vs = sm + PV_V + buf*4352;
    int j0 = jt << 6;

    {
      float runv = 0.f; int runb = -1;
      #pragma unroll
      for (int q = 0; q < 16; q++){
        int jj = q0 + q;
        int idx = sr*68 + jj;
        float pvv = __uint_as_float(f2tf32(fexp(ps[idx] - msr)));
        ps[idx] = pvv;
        int j = j0 + jj;
        int dy = syi - (j>>5), dx = sxi - (j&31);
        int bkt = ((int)c_pidx[dy+31]+4)*9 + ((int)c_pidx[dx+31]+4);
        if (bkt == runb) runv += pvv;
        else {
          if (runb >= 0) atomicAdd(&sb[sr*88 + runb], runv);
          runb = bkt; runv = pvv;
        }
      }
      atomicAdd(&sb[sr*88 + runb], runv);
    }
    __syncthreads();

    #pragma unroll
    for (int ks = 0; ks < 64; ks += 8){
      uint32_t af[2][4], bf[2][2];
      #pragma unroll
      for (int mt = 0; mt < 2; mt++){
        int r0 = wm + (mt<<4) + g;
        af[mt][0] = __float_as_uint(ps[ r0   *68 + ks+tg  ]);
        af[mt][1] = __float_as_uint(ps[(r0+8)*68 + ks+tg  ]);
        af[mt][2] = __float_as_uint(ps[ r0   *68 + ks+tg+4]);
        af[mt][3] = __float_as_uint(ps[(r0+8)*68 + ks+tg+4]);
      }
      #pragma unroll
      for (int nt = 0; nt < 2; nt++){
        int n = wn + (nt<<3) + g;
        bf[nt][0] = __float_as_uint(vs[(ks+tg  )*68 + n]);
        bf[nt][1] = __float_as_uint(vs[(ks+tg+4)*68 + n]);
      }
      #pragma unroll
      for (int mt = 0; mt < 2; mt++)
        #pragma unroll
        for (int nt = 0; nt < 2; nt++)
          mma_tf32(acc[mt][nt], af[mt], bf[nt]);
    }
    __syncthreads();
  }

  float* tvs = sm + PV_TVS;
  for (int f = t; f < 88*68; f += 256) tvs[f] = 0.f;
  __syncthreads();
  for (int f = t; f < NBKT*64; f += 256){
    int c = f >> 6, d = f & 63;
    tvs[c*68 + d] = __uint_as_float(f2tf32(tv[f]));
  }
  if (t < 64){
    float ssum = 0.f;
    #pragma unroll
    for (int c = 0; c < NBKT; c++) ssum += sb[t*88 + c];
    rsv[t] = 1.0f / ssum;
  }
  __syncthreads();

  #pragma unroll
  for (int ks = 0; ks < 88; ks += 8){
    uint32_t af[2][4], bf[2][2];
    #pragma unroll
    for (int mt = 0; mt < 2; mt++){
      int r0 = wm + (mt<<4) + g;
      af[mt][0] = __float_as_uint(sb[ r0   *88 + ks+tg  ]);
      af[mt][1] = __float_as_uint(sb[(r0+8)*88 + ks+tg  ]);
      af[mt][2] = __float_as_uint(sb[ r0   *88 + ks+tg+4]);
      af[mt][3] = __float_as_uint(sb[(r0+8)*88 + ks+tg+4]);
    }
    #pragma unroll
    for (int nt = 0; nt < 2; nt++){
      int n = wn + (nt<<3) + g;
      bf[nt][0] = __float_as_uint(tvs[(ks+tg  )*68 + n]);
      bf[nt][1] = __float_as_uint(tvs[(ks+tg+4)*68 + n]);
    }
    #pragma unroll
    for (int mt = 0; mt < 2; mt++)
      #pragma unroll
      for (int nt = 0; nt < 2; nt++)
        mma_tf32(acc[mt][nt], af[mt], bf[nt]);
  }

  #pragma unroll
  for (int mt = 0; mt < 2; mt++){
    #pragma unroll
    for (int hh = 0; hh < 2; hh++){
      int r = wm + (mt<<4) + g + (hh<<3);
      float inv = rsv[r];
      #pragma unroll
      for (int nt = 0; nt < 2; nt++){
        int col = wn + (nt<<3) + (tg<<1);
        float o0 = acc[mt][nt][hh*2+0] * inv;
        float o1 = acc[mt][nt][hh*2+1] * inv;
        float* op = out + ((size_t)(b<<10) + i0 + r)*CDIM + (h<<6) + col;
        *(float2*)op = make_float2(o0, o1);
      }
    }
  }
}

// ---------------- launch ----------------------------------------------------
extern "C" void kernel_launch(void* const* d_in, const int* in_sizes, int n_in,
                              void* d_out, int out_size)
{
  const float* x0     = (const float*)d_in[0];
  const float* x1     = (const float*)d_in[1];
  const float* ln00_g = (const float*)d_in[2];
  const float* ln00_b = (const float*)d_in[3];
  const float* ln01_g = (const float*)d_in[4];
  const float* ln01_b = (const float*)d_in[5];
  const float* ln10_g = (const float*)d_in[6];
  const float* ln10_b = (const float*)d_in[7];
  const float* ln11_g = (const float*)d_in[8];
  const float* ln11_b = (const float*)d_in[9];
  const float* w_qkv0 = (const float*)d_in[10];
  const float* b_qkv0 = (const float*)d_in[11];
  const float* w_qkv1 = (const float*)d_in[12];
  const float* b_qkv1 = (const float*)d_in[13];
  const float* w_proj = (const float*)d_in[14];
  const float* b_proj = (const float*)d_in[15];
  const float* table_q= (const float*)d_in[16];
  const float* table_k= (const float*)d_in[17];
  const float* table_v= (const float*)d_in[18];
  const float* w_fc1_0= (const float*)d_in[19];
  const float* b_fc1_0= (const float*)d_in[20];
  const float* w_fc2_0= (const float*)d_in[21];
  const float* b_fc2_0= (const float*)d_in[22];
  const float* w_fc1_1= (const float*)d_in[23];
  const float* b_fc1_1= (const float*)d_in[24];
  const float* w_fc2_1= (const float*)d_in[25];
  const float* b_fc2_1= (const float*)d_in[26];

  float* out0 = (float*)d_out;
  float* out1 = (float*)d_out + (size_t)ROWS*CDIM;

  float *ln0, *ln1, *qkv0, *qkv1, *att0, *att1, *lk0, *lk1, *lq0, *lq1;
  float *lg0, *lg1, *ml0, *ml1, *hid0, *hid1;
  cudaGetSymbolAddress((void**)&ln0,  g_ln);     ln1  = ln0  + (size_t)ROWS*CDIM;
  cudaGetSymbolAddress((void**)&qkv0, g_qkv);    qkv1 = qkv0 + (size_t)ROWS*QKVD;
  cudaGetSymbolAddress((void**)&att0, g_att);    att1 = att0 + (size_t)ROWS*CDIM;
  cudaGetSymbolAddress((void**)&lk0,  g_lk);     lk1  = lk0  + (size_t)BHN*NBKT;
  cudaGetSymbolAddress((void**)&lq0,  g_lq);     lq1  = lq0  + (size_t)BHN*NBKT;
  cudaGetSymbolAddress((void**)&lg0,  g_logits); lg1  = lg0  + (size_t)32*NQ*NQ;
  cudaGetSymbolAddress((void**)&ml0,  g_ml);     ml1  = ml0  + (size_t)BHN;
  cudaGetSymbolAddress((void**)&hid0, g_hid);    hid1 = hid0 + (size_t)ROWS*HID;

  const int LOGITS_SMEM = 18944 * 4;
  const int PV_SMEM     = PV_SMEM_FLOATS * 4;
  static int attr_done = 0;
  if (!attr_done){
    cudaFuncSetAttribute(logits_kernel, cudaFuncAttributeMaxDynamicSharedMemorySize, LOGITS_SMEM);
    cudaFuncSetAttribute(pv_kernel,     cudaFuncAttributeMaxDynamicSharedMemorySize, PV_SMEM);
    attr_done = 1;
  }

  // 1. LN (both streams) + ml init
  dim3 gln(ROWS, 2);
  ln_kernel<<<gln, 128>>>(x0, x1, ln00_g, ln01_g, ln00_b, ln01_b, ln0, ln1);
  mlinit_kernel<<<(2*BHN)/256, 256>>>(ml0);

  // 2. qkv GEMMs (paired, BN=128)
  {
    GemmPtrs p{{ln0, ln1},{w_qkv0, w_qkv1},{b_qkv0, b_qkv1},{nullptr,nullptr},{qkv0, qkv1}};
    dim3 gg(QKVD/128, ROWS/128, 2);
    sgemm_tf32_kernel<128><<<gg, 256>>>(p, ROWS, QKVD, CDIM, 0);
  }

  // 3. bias tables
  dim3 gbt(BHN/64, 2, 2);
  biastab_kernel<<<gbt, 256>>>(qkv0, qkv1, table_q, table_k, lk0, lk1, lq0, lq1);

  // 4. logits + fused row max
  dim3 glg(16, 16, 64);
  logits_kernel<<<glg, 256, LOGITS_SMEM>>>(qkv0, qkv1, lk0, lk1, lq0, lq1,
                                           lg0, lg1, ml0, ml1);

  // 5. PV + tv table
  dim3 gpv(16, 64);
  pv_kernel<<<gpv, 256, PV_SMEM>>>(lg0, lg1, ml0, ml1, qkv0, qkv1, table_v, att0, att1);

  // 6. proj + residual (paired, BN=64)
  {
    GemmPtrs p{{att0, att1},{w_proj, w_proj},{b_proj, b_proj},{x0, x1},{out0, out1}};
    dim3 gg(CDIM/64, ROWS/128, 2);
    sgemm_tf32_kernel<64><<<gg, 256>>>(p, ROWS, CDIM, CDIM, 0);
  }

  // 7. MLP
  ln_kernel<<<gln, 128>>>(out0, out1, ln10_g, ln11_g, ln10_b, ln11_b, ln0, ln1);

  {
    GemmPtrs p{{ln0, ln1},{w_fc1_0, w_fc1_1},{b_fc1_0, b_fc1_1},{nullptr,nullptr},{hid0, hid1}};
    dim3 gg(HID/128, ROWS/128, 2);
    sgemm_tf32_kernel<128><<<gg, 256>>>(p, ROWS, HID, CDIM, 1);
  }
  {
    GemmPtrs p{{hid0, hid1},{w_fc2_0, w_fc2_1},{b_fc2_0, b_fc2_1},{out0, out1},{out0, out1}};
    dim3 gg(CDIM/64, ROWS/128, 2);
    sgemm_tf32_kernel<64><<<gg, 256>>>(p, ROWS, CDIM, HID, 0);
  }
}

// round 14
// speedup vs baseline: 1.7573x; 1.0830x over previous
#include <cuda_runtime.h>
#include <cuda_bf16.h>
#include <math.h>
#include <stdint.h>

// ---------------- problem constants ----------------
#define ROWS 4096        // B*N
#define CDIM 512
#define QKVD 1536
#define HID  2048
#define NHEAD 8
#define HD   64
#define NQ   1024
#define BHN  32768       // B*H*N
#define NBKT 81
#define LSTR 88          // bf16 bias-table row stride (16B-aligned)

// ---------------- device scratch ----------------
__device__ float g_ln    [2][ROWS*CDIM];
__device__ float g_qkv   [2][ROWS*QKVD];
__device__ float g_att   [2][ROWS*CDIM];
__device__ __nv_bfloat16 g_lkb[2][(size_t)BHN*LSTR];
__device__ __nv_bfloat16 g_lqb[2][(size_t)BHN*LSTR];
__device__ float g_logits[2][(size_t)32*NQ*NQ];
__device__ float g_ml    [2][BHN];
__device__ float g_hid   [2][(size_t)ROWS*HID];

__constant__ signed char c_pidx[63] = {
  -4,-4,-4,-4,-4,-4,-4,-4,-4,-4,-4,-4,-4,-4,-4,-4,-4,-4,-4,-4,-4,
  -3,-3,-3,-3,-3,-3,-3,
  -2,-2,
  -1,
   0,
   1,
   2, 2,
   3, 3, 3, 3, 3, 3, 3,
   4, 4, 4, 4, 4, 4, 4, 4, 4, 4, 4, 4, 4, 4, 4, 4, 4, 4, 4, 4, 4
};

__device__ __forceinline__ float fexp(float x){
  float y = x * 1.4426950408889634f;
  float n = rintf(y);
  float f = y - n;
  float p =           1.3333558e-3f;
  p = fmaf(p, f, 9.6181291e-3f);
  p = fmaf(p, f, 5.5504108e-2f);
  p = fmaf(p, f, 2.4022650e-1f);
  p = fmaf(p, f, 6.9314718e-1f);
  p = fmaf(p, f, 1.0f);
  int ni = (int)n;
  return p * __int_as_float((ni + 127) << 23);
}

__device__ __forceinline__ uint32_t f2tf32(float v){
  uint32_t r;
  asm("cvt.rna.tf32.f32 %0, %1;" : "=r"(r) : "f"(v));
  return r;
}

__device__ __forceinline__ void mma_tf32(float* c, const uint32_t* a, const uint32_t* b){
  asm volatile(
    "mma.sync.aligned.m16n8k8.row.col.f32.tf32.tf32.f32 "
    "{%0,%1,%2,%3}, {%4,%5,%6,%7}, {%8,%9}, {%0,%1,%2,%3};"
    : "+f"(c[0]), "+f"(c[1]), "+f"(c[2]), "+f"(c[3])
    : "r"(a[0]), "r"(a[1]), "r"(a[2]), "r"(a[3]), "r"(b[0]), "r"(b[1]));
}

__device__ __forceinline__ void cp16(uint32_t dst, const void* src){
  asm volatile("cp.async.cg.shared.global [%0], [%1], 16;\n" :: "r"(dst), "l"(src));
}

struct GemmPtrs {
  const float* A[2];
  const float* B[2];
  const float* bias[2];
  const float* resid[2];
  float* C[2];
};

// ---------------- layernorm (paired streams) --------------------------------
__global__ void ln_kernel(const float* __restrict__ x0, const float* __restrict__ x1,
                          const float* __restrict__ g0, const float* __restrict__ g1,
                          const float* __restrict__ be0, const float* __restrict__ be1,
                          float* __restrict__ y0, float* __restrict__ y1)
{
  int sIdx = blockIdx.y;
  const float* x  = sIdx ? x1 : x0;
  const float* gam= sIdx ? g1 : g0;
  const float* bet= sIdx ? be1 : be0;
  float* y        = sIdx ? y1 : y0;
  int row = blockIdx.x;
  int t = threadIdx.x;
  const float* xr = x + (size_t)row * CDIM;
  float4 v = *(const float4*)(xr + t*4);
  float s  = v.x + v.y + v.z + v.w;
  float s2 = v.x*v.x + v.y*v.y + v.z*v.z + v.w*v.w;
  #pragma unroll
  for (int o = 16; o > 0; o >>= 1){
    s  += __shfl_xor_sync(0xffffffffu, s , o);
    s2 += __shfl_xor_sync(0xffffffffu, s2, o);
  }
  __shared__ float rs[4], rq[4];
  if ((t & 31) == 0){ rs[t>>5] = s; rq[t>>5] = s2; }
  __syncthreads();
  s  = rs[0]+rs[1]+rs[2]+rs[3];
  s2 = rq[0]+rq[1]+rq[2]+rq[3];
  float mu   = s  * (1.0f/CDIM);
  float var  = s2 * (1.0f/CDIM) - mu*mu;
  float rstd = rsqrtf(var + 1e-5f);
  float4 g4 = *(const float4*)(gam + t*4);
  float4 b4 = *(const float4*)(bet + t*4);
  float4 o4;
  o4.x = (v.x-mu)*rstd*g4.x + b4.x;
  o4.y = (v.y-mu)*rstd*g4.y + b4.y;
  o4.z = (v.z-mu)*rstd*g4.z + b4.z;
  o4.w = (v.w-mu)*rstd*g4.w + b4.w;
  *(float4*)(y + (size_t)row*CDIM + t*4) = o4;
}

// ---------------- tf32 GEMM, cp.async double-buffered, BN templated --------
template <int BN>
__global__ void __launch_bounds__(256, 2) sgemm_tf32_kernel(
    GemmPtrs p, int M, int N, int K, int gelu)
{
  constexpr int BSTR = BN + 4;
  constexpr int MT = (BN == 128) ? 4 : 2;
  constexpr int NT = 4;
  constexpr int NBCH = (BN == 128) ? 2 : 1;
  __shared__ float As[2][128*20];
  __shared__ float Bs[2][16*BSTR];
  int t = threadIdx.x;
  int z = blockIdx.z;
  const float* A     = p.A[z];
  const float* Bm    = p.B[z];
  const float* bias  = p.bias[z];
  const float* resid = p.resid[z];
  float* C           = p.C[z];

  int bn = blockIdx.x * BN;
  int bm = blockIdx.y * 128;
  int warp = t >> 5, lane = t & 31;
  int wm, wn;
  if (BN == 128){ wm = (warp >> 2) << 6; wn = (warp & 3) << 5; }
  else          { wm = (warp >> 1) << 5; wn = (warp & 1) << 5; }
  int g  = lane >> 2;
  int tg = lane & 3;

  float acc[MT][NT][4];
  #pragma unroll
  for (int mt=0;mt<MT;mt++)
    #pragma unroll
    for (int nt=0;nt<NT;nt++)
      #pragma unroll
      for (int c=0;c<4;c++) acc[mt][nt][c] = 0.f;

  const float* Ag = A + (size_t)bm * K;
  const float* Bg = Bm + bn;

  uint32_t asb[2], bsb[2];
  asb[0] = (uint32_t)__cvta_generic_to_shared(&As[0][0]);
  asb[1] = (uint32_t)__cvta_generic_to_shared(&As[1][0]);
  bsb[0] = (uint32_t)__cvta_generic_to_shared(&Bs[0][0]);
  bsb[1] = (uint32_t)__cvta_generic_to_shared(&Bs[1][0]);

  int ar[2], as4[2], bkr[NBCH], bnc[NBCH];
  #pragma unroll
  for (int i = 0; i < 2; i++){
    int c = t + (i<<8);
    ar[i]  = c >> 2;  as4[i] = (c & 3) << 2;
  }
  #pragma unroll
  for (int i = 0; i < NBCH; i++){
    int c = t + (i<<8);
    if (BN == 128){ bkr[i] = c >> 5; bnc[i] = (c & 31) << 2; }
    else          { bkr[i] = c >> 4; bnc[i] = (c & 15) << 2; }
  }

  int ntiles = K >> 4;
  #pragma unroll
  for (int i = 0; i < 2; i++)
    cp16(asb[0] + ((ar[i]*20 + as4[i])<<2), Ag + (size_t)ar[i]*K + as4[i]);
  #pragma unroll
  for (int i = 0; i < NBCH; i++)
    cp16(bsb[0] + ((bkr[i]*BSTR + bnc[i])<<2), Bg + (size_t)bkr[i]*N + bnc[i]);
  asm volatile("cp.async.commit_group;\n");

  for (int it = 0; it < ntiles; it++){
    int buf = it & 1;
    if (it + 1 < ntiles){
      int k0 = (it+1) << 4;
      int nb = (it+1) & 1;
      #pragma unroll
      for (int i = 0; i < 2; i++)
        cp16(asb[nb] + ((ar[i]*20 + as4[i])<<2), Ag + (size_t)ar[i]*K + k0 + as4[i]);
      #pragma unroll
      for (int i = 0; i < NBCH; i++)
        cp16(bsb[nb] + ((bkr[i]*BSTR + bnc[i])<<2), Bg + (size_t)(k0 + bkr[i])*N + bnc[i]);
    }
    asm volatile("cp.async.commit_group;\n");
    asm volatile("cp.async.wait_group 1;\n");
    __syncthreads();

    const float* Ab = As[buf];
    const float* Bb = Bs[buf];
    #pragma unroll
    for (int ks = 0; ks < 16; ks += 8){
      uint32_t af[MT][4], bf[NT][2];
      #pragma unroll
      for (int mt = 0; mt < MT; mt++){
        int m = wm + (mt<<4) + g;
        af[mt][0] = __float_as_uint(Ab[ m   *20 + ks+tg  ]);
        af[mt][1] = __float_as_uint(Ab[(m+8)*20 + ks+tg  ]);
        af[mt][2] = __float_as_uint(Ab[ m   *20 + ks+tg+4]);
        af[mt][3] = __float_as_uint(Ab[(m+8)*20 + ks+tg+4]);
      }
      #pragma unroll
      for (int nt = 0; nt < NT; nt++){
        int n = wn + (nt<<3) + g;
        bf[nt][0] = __float_as_uint(Bb[(ks+tg  )*BSTR + n]);
        bf[nt][1] = __float_as_uint(Bb[(ks+tg+4)*BSTR + n]);
      }
      #pragma unroll
      for (int mt = 0; mt < MT; mt++)
        #pragma unroll
        for (int nt = 0; nt < NT; nt++)
          mma_tf32(acc[mt][nt], af[mt], bf[nt]);
    }
    __syncthreads();
  }

  #pragma unroll
  for (int mt = 0; mt < MT; mt++){
    int row0 = bm + wm + (mt<<4) + g;
    #pragma unroll
    for (int nt = 0; nt < NT; nt++){
      int col = bn + wn + (nt<<3) + (tg<<1);
      float b0 = bias[col], b1 = bias[col+1];
      #pragma unroll
      for (int h = 0; h < 2; h++){
        int row = row0 + (h<<3);
        float r0 = acc[mt][nt][h*2+0] + b0;
        float r1 = acc[mt][nt][h*2+1] + b1;
        if (gelu){
          r0 = 0.5f*r0*(1.0f + erff(r0*0.70710678f));
          r1 = 0.5f*r1*(1.0f + erff(r1*0.70710678f));
        }
        if (resid){
          const float2 rr = *(const float2*)(resid + (size_t)row*N + col);
          r0 += rr.x; r1 += rr.y;
        }
        *(float2*)(C + (size_t)row*N + col) = make_float2(r0, r1);
      }
    }
  }
}

// ---------------- bias tables as tiled GEMM (bf16 output, stride 88) --------
__global__ void __launch_bounds__(256) biastab_kernel(
    const float* __restrict__ qkv0, const float* __restrict__ qkv1,
    const float* __restrict__ tq, const float* __restrict__ tk,
    __nv_bfloat16* __restrict__ lk0, __nv_bfloat16* __restrict__ lk1,
    __nv_bfloat16* __restrict__ lq0, __nv_bfloat16* __restrict__ lq1)
{
  __shared__ float qs[64*65];
  __shared__ float tabT[64*84];

  int t = threadIdx.x;
  int s = blockIdx.z, which = blockIdx.y;
  int base = blockIdx.x << 6;
  const float* src;
  float scl;
  if (which == 0){ src = (s == 0 ? qkv0 : qkv1);       scl = 1.0f;   }
  else           { src = (s == 0 ? qkv1 : qkv0) + 512; scl = 0.125f; }
  const float* tab = (which == 0) ? tk : tq;

  for (int idx = t; idx < NBKT*64; idx += 256){
    int c = idx >> 6, d = idx & 63;
    tabT[d*84 + c] = tab[idx];
  }
  #pragma unroll
  for (int it = 0; it < 4; it++){
    int f = t + (it<<8);
    int r = f >> 4, c4 = (f & 15) << 2;
    int rid = base + r;
    int bh = rid >> 10, n = rid & 1023;
    int b = bh >> 3, h = bh & 7;
    float4 v = *(const float4*)(src + (size_t)((b<<10)+n)*QKVD + (h<<6) + c4);
    qs[r*65+c4+0] = scl*v.x; qs[r*65+c4+1] = scl*v.y;
    qs[r*65+c4+2] = scl*v.z; qs[r*65+c4+3] = scl*v.w;
  }
  __syncthreads();

  int tx = t & 31, ty = t >> 5;
  float acc[8][3];
  #pragma unroll
  for (int i=0;i<8;i++){ acc[i][0]=0.f; acc[i][1]=0.f; acc[i][2]=0.f; }

  #pragma unroll 8
  for (int k = 0; k < 64; k++){
    float b0 = tabT[k*84 + tx];
    float b1 = tabT[k*84 + tx + 32];
    float b2 = (tx < 17) ? tabT[k*84 + tx + 64] : 0.f;
    #pragma unroll
    for (int i = 0; i < 8; i++){
      float a = qs[((ty<<3)+i)*65 + k];
      acc[i][0] = fmaf(a, b0, acc[i][0]);
      acc[i][1] = fmaf(a, b1, acc[i][1]);
      acc[i][2] = fmaf(a, b2, acc[i][2]);
    }
  }

  __nv_bfloat16* dstbase = (which == 0) ? (s == 0 ? lk0 : lk1) : (s == 0 ? lq0 : lq1);
  #pragma unroll
  for (int i = 0; i < 8; i++){
    int rid = base + (ty<<3) + i;
    __nv_bfloat16* dst = dstbase + (size_t)rid*LSTR;
    dst[tx]      = __float2bfloat16(acc[i][0]);
    dst[tx + 32] = __float2bfloat16(acc[i][1]);
    if (tx < 17) dst[tx + 64] = __float2bfloat16(acc[i][2]);
  }
}

// ---------------- strip logits: 64 rows x 1024 j, cp.async pipelined -------
// smem floats: qs[64*65]@0, ks 2x[64*68]@4160, lks(bf16 as 2816f)@12864,
//              lqs(bf16) 2x2816f @15680, rmx[256]@21312 ; total 21568 floats
#define LG_QS   0
#define LG_KS   4160
#define LG_KSZ  4352
#define LG_LKS  12864
#define LG_LQS  15680
#define LG_LQZ  2816
#define LG_RMX  21312
#define LG_SMEM_FLOATS 21568

__global__ void __launch_bounds__(256, 2) logits_kernel(
    const float* __restrict__ qkv0, const float* __restrict__ qkv1,
    const __nv_bfloat16* __restrict__ lk0, const __nv_bfloat16* __restrict__ lk1,
    const __nv_bfloat16* __restrict__ lq0, const __nv_bfloat16* __restrict__ lq1,
    float* __restrict__ lg0, float* __restrict__ lg1,
    float* __restrict__ ml0, float* __restrict__ ml1)
{
  extern __shared__ float sm[];
  float* qs = sm + LG_QS;
  __nv_bfloat16* lks = (__nv_bfloat16*)(sm + LG_LKS);
  float* rmx = sm + LG_RMX;

  int t = threadIdx.x;
  int zs = blockIdx.y;
  int s = zs >> 5;
  int bh = zs & 31; int b = bh>>3, h = bh&7;
  int i0 = blockIdx.x << 6;
  size_t rbase = ((size_t)bh)<<10;

  const float* qkv_q  = (s==0) ? qkv0 : qkv1;
  const float* qkv_kv = (s==0) ? qkv1 : qkv0;
  const __nv_bfloat16* LKb = (s==0) ? lk0 : lk1;
  const __nv_bfloat16* LQb = (s==0) ? lq0 : lq1;
  float* S  = (s==0) ? lg0 : lg1;
  float* ML = (s==0) ? ml0 : ml1;

  const float* qb = qkv_q  + (size_t)(b<<10)*QKVD + (h<<6);
  const float* kb = qkv_kv + (size_t)(b<<10)*QKVD + (h<<6) + 512;

  uint32_t ksb[2], lqsb[2];
  ksb[0]  = (uint32_t)__cvta_generic_to_shared(sm + LG_KS);
  ksb[1]  = (uint32_t)__cvta_generic_to_shared(sm + LG_KS + LG_KSZ);
  lqsb[0] = (uint32_t)__cvta_generic_to_shared(sm + LG_LQS);
  lqsb[1] = (uint32_t)__cvta_generic_to_shared(sm + LG_LQS + LG_LQZ);
  uint32_t lksb = (uint32_t)__cvta_generic_to_shared(sm + LG_LKS);

  // prologue: lks (once), K tile0, LQ tile0 via cp.async
  for (int f = t; f < 704; f += 256){
    int r = f / 11, c8 = (f - r*11) << 3;
    cp16(lksb + ((r*LSTR + c8)<<1), LKb + (rbase + i0 + r)*LSTR + c8);
  }
  #pragma unroll
  for (int i = 0; i < 4; i++){
    int f = t + (i<<8);
    int r = f >> 4, c4 = (f & 15) << 2;
    cp16(ksb[0] + ((r*68 + c4)<<2), kb + (size_t)r*QKVD + c4);
  }
  for (int f = t; f < 704; f += 256){
    int r = f / 11, c8 = (f - r*11) << 3;
    cp16(lqsb[0] + ((r*LSTR + c8)<<1), LQb + (rbase + r)*LSTR + c8);
  }
  asm volatile("cp.async.commit_group;\n");

  // Q staged synchronously (once)
  #pragma unroll
  for (int it = 0; it < 4; it++){
    int f = t + (it<<8);
    int r = f >> 4, c4 = (f & 15) << 2;
    float4 qv = *(const float4*)(qb + (size_t)(i0+r)*QKVD + c4);
    qs[r*65+c4+0]=qv.x; qs[r*65+c4+1]=qv.y;
    qs[r*65+c4+2]=qv.z; qs[r*65+c4+3]=qv.w;
  }

  int warp = t >> 5, lane = t & 31;
  int g = lane >> 2, tg = lane & 3;
  int wm = (warp >> 2) << 5;
  int wn = (warp & 3) << 4;

  float rml[2][2];
  rml[0][0] = rml[0][1] = rml[1][0] = rml[1][1] = -1e30f;

  for (int jt = 0; jt < 16; jt++){
    int buf = jt & 1;
    if (jt + 1 < 16){
      int j0n = (jt+1) << 6;
      int nb = (jt+1) & 1;
      #pragma unroll
      for (int i = 0; i < 4; i++){
        int f = t + (i<<8);
        int r = f >> 4, c4 = (f & 15) << 2;
        cp16(ksb[nb] + ((r*68 + c4)<<2), kb + (size_t)(j0n+r)*QKVD + c4);
      }
      for (int f = t; f < 704; f += 256){
        int r = f / 11, c8 = (f - r*11) << 3;
        cp16(lqsb[nb] + ((r*LSTR + c8)<<1), LQb + (rbase + j0n + r)*LSTR + c8);
      }
    }
    asm volatile("cp.async.commit_group;\n");
    asm volatile("cp.async.wait_group 1;\n");
    __syncthreads();

    const float* ks = sm + LG_KS + buf*LG_KSZ;
    const __nv_bfloat16* lqs = (const __nv_bfloat16*)(sm + LG_LQS + buf*LG_LQZ);
    int j0 = jt << 6;

    float acc[2][2][4];
    #pragma unroll
    for (int mt=0;mt<2;mt++)
      #pragma unroll
      for (int nt=0;nt<2;nt++)
        #pragma unroll
        for (int c=0;c<4;c++) acc[mt][nt][c]=0.f;

    #pragma unroll
    for (int kk = 0; kk < 64; kk += 8){
      uint32_t af[2][4], bf[2][2];
      #pragma unroll
      for (int mt = 0; mt < 2; mt++){
        int r0 = wm + (mt<<4) + g;
        af[mt][0] = __float_as_uint(qs[ r0   *65 + kk+tg  ]);
        af[mt][1] = __float_as_uint(qs[(r0+8)*65 + kk+tg  ]);
        af[mt][2] = __float_as_uint(qs[ r0   *65 + kk+tg+4]);
        af[mt][3] = __float_as_uint(qs[(r0+8)*65 + kk+tg+4]);
      }
      #pragma unroll
      for (int nt = 0; nt < 2; nt++){
        int n = wn + (nt<<3) + g;
        bf[nt][0] = __float_as_uint(ks[n*68 + kk+tg  ]);
        bf[nt][1] = __float_as_uint(ks[n*68 + kk+tg+4]);
      }
      #pragma unroll
      for (int mt = 0; mt < 2; mt++)
        #pragma unroll
        for (int nt = 0; nt < 2; nt++)
          mma_tf32(acc[mt][nt], af[mt], bf[nt]);
    }

    #pragma unroll
    for (int mt = 0; mt < 2; mt++){
      #pragma unroll
      for (int hh = 0; hh < 2; hh++){
        int il = wm + (mt<<4) + g + (hh<<3);
        int i = i0 + il;
        int yi = i >> 5, xi = i & 31;
        const __nv_bfloat16* lkrow = lks + il*LSTR;
        #pragma unroll
        for (int nt = 0; nt < 2; nt++){
          int jl = wn + (nt<<3) + (tg<<1);
          int j = j0 + jl;
          int dy0 = yi - (j>>5),     dx0 = xi - (j&31);
          int dy1 = yi - ((j+1)>>5), dx1 = xi - ((j+1)&31);
          int bkt0 = ((int)c_pidx[dy0+31]+4)*9 + ((int)c_pidx[dx0+31]+4);
          int bkt1 = ((int)c_pidx[dy1+31]+4)*9 + ((int)c_pidx[dx1+31]+4);
          float v0 = acc[mt][nt][hh*2+0]*0.125f + __bfloat162float(lkrow[bkt0])
                   + __bfloat162float(lqs[jl*LSTR + 80 - bkt0]);
          float v1 = acc[mt][nt][hh*2+1]*0.125f + __bfloat162float(lkrow[bkt1])
                   + __bfloat162float(lqs[(jl+1)*LSTR + 80 - bkt1]);
          *(float2*)(S + (rbase + i)*NQ + j) = make_float2(v0, v1);
          rml[mt][hh] = fmaxf(rml[mt][hh], fmaxf(v0, v1));
        }
      }
    }
    __syncthreads();
  }

  // row max (full row in-block): shfl over tg lanes, combine 4 warp columns
  #pragma unroll
  for (int mt = 0; mt < 2; mt++){
    #pragma unroll
    for (int hh = 0; hh < 2; hh++){
      float rm = rml[mt][hh];
      rm = fmaxf(rm, __shfl_xor_sync(0xffffffffu, rm, 1));
      rm = fmaxf(rm, __shfl_xor_sync(0xffffffffu, rm, 2));
      if (tg == 0){
        int il = wm + (mt<<4) + g + (hh<<3);
        rmx[(il<<2) + (warp & 3)] = rm;
      }
    }
  }
  __syncthreads();
  if (t < 64){
    float m = fmaxf(fmaxf(rmx[t<<2], rmx[(t<<2)+1]),
                    fmaxf(rmx[(t<<2)+2], rmx[(t<<2)+3]));
    ML[rbase + i0 + t] = m;
  }
}

// ---------------- PV: cp.async double-buffered + scatter + tv-GEMM ---------
#define PV_S    0
#define PV_V    8704
#define PV_SB   17408
#define PV_MROW 23040
#define PV_RSV  23104
#define PV_TVS  8704
#define PV_SMEM_FLOATS 23168

__global__ void __launch_bounds__(256) pv_kernel(
    const float* __restrict__ lg0, const float* __restrict__ lg1,
    const float* __restrict__ ml0, const float* __restrict__ ml1,
    const float* __restrict__ qkv0, const float* __restrict__ qkv1,
    const float* __restrict__ tv,
    float* __restrict__ att0, float* __restrict__ att1)
{
  extern __shared__ float sm[];
  float* sb  = sm + PV_SB;
  float* mrow= sm + PV_MROW;
  float* rsv = sm + PV_RSV;

  int t = threadIdx.x;
  int zy = blockIdx.y;
  int s = zy >> 5;
  int bh = zy & 31; int b = bh>>3, h = bh&7;
  int i0 = blockIdx.x << 6;
  size_t rb2 = (((size_t)bh)<<10) + i0;

  const float* S  = (s==0) ? lg0 : lg1;
  const float* ml = (s==0) ? ml0 : ml1;
  const float* qkv_kv = (s==0) ? qkv1 : qkv0;
  float* out = (s==0) ? att0 : att1;

  if (t < 64) mrow[t] = ml[rb2 + t];
  for (int f = t; f < 64*88; f += 256) sb[f] = 0.f;

  const float* vb = qkv_kv + ((size_t)(b<<10))*QKVD + (h<<6) + 1024;

  uint32_t sbs[2], vbs[2];
  sbs[0] = (uint32_t)__cvta_generic_to_shared(sm + PV_S);
  sbs[1] = (uint32_t)__cvta_generic_to_shared(sm + PV_S + 4352);
  vbs[0] = (uint32_t)__cvta_generic_to_shared(sm + PV_V);
  vbs[1] = (uint32_t)__cvta_generic_to_shared(sm + PV_V + 4352);

  int cr[4], cc4[4];
  #pragma unroll
  for (int i = 0; i < 4; i++){
    int f = t + (i<<8);
    cr[i] = f >> 4; cc4[i] = (f & 15) << 2;
  }

  #pragma unroll
  for (int i = 0; i < 4; i++){
    cp16(sbs[0] + ((cr[i]*68 + cc4[i])<<2), S + (rb2 + cr[i])*NQ + cc4[i]);
    cp16(vbs[0] + ((cr[i]*68 + cc4[i])<<2), vb + (size_t)cr[i]*QKVD + cc4[i]);
  }
  asm volatile("cp.async.commit_group;\n");
  __syncthreads();

  int warp = t >> 5, lane = t & 31;
  int g = lane >> 2, tg = lane & 3;
  int wm = (warp >> 2) << 5;
  int wn = (warp & 3) << 4;

  float acc[2][2][4];
  #pragma unroll
  for (int mt=0;mt<2;mt++)
    #pragma unroll
    for (int nt=0;nt<2;nt++)
      #pragma unroll
      for (int c=0;c<4;c++) acc[mt][nt][c]=0.f;

  int sr = t >> 2;
  int q0 = (t & 3) << 4;
  int iglob = i0 + sr;
  int syi = iglob >> 5, sxi = iglob & 31;
  float msr = mrow[sr];

  for (int jt = 0; jt < 16; jt++){
    int buf = jt & 1;
    if (jt + 1 < 16){
      int j0n = (jt+1) << 6;
      int nb = (jt+1) & 1;
      #pragma unroll
      for (int i = 0; i < 4; i++){
        cp16(sbs[nb] + ((cr[i]*68 + cc4[i])<<2), S + (rb2 + cr[i])*NQ + j0n + cc4[i]);
        cp16(vbs[nb] + ((cr[i]*68 + cc4[i])<<2), vb + (size_t)(j0n + cr[i])*QKVD + cc4[i]);
      }
    }
    asm volatile("cp.async.commit_group;\n");
    asm volatile("cp.async.wait_group 1;\n");
    __syncthreads();

    float* ps = sm + PV_S + buf*4352;
    float* vs = sm + PV_V + buf*4352;
    int j0 = jt << 6;

    {
      float runv = 0.f; int runb = -1;
      #pragma unroll
      for (int q = 0; q < 16; q++){
        int jj = q0 + q;
        int idx = sr*68 + jj;
        float pvv = __uint_as_float(f2tf32(fexp(ps[idx] - msr)));
        ps[idx] = pvv;
        int j = j0 + jj;
        int dy = syi - (j>>5), dx = sxi - (j&31);
        int bkt = ((int)c_pidx[dy+31]+4)*9 + ((int)c_pidx[dx+31]+4);
        if (bkt == runb) runv += pvv;
        else {
          if (runb >= 0) atomicAdd(&sb[sr*88 + runb], runv);
          runb = bkt; runv = pvv;
        }
      }
      atomicAdd(&sb[sr*88 + runb], runv);
    }
    __syncthreads();

    #pragma unroll
    for (int ks = 0; ks < 64; ks += 8){
      uint32_t af[2][4], bf[2][2];
      #pragma unroll
      for (int mt = 0; mt < 2; mt++){
        int r0 = wm + (mt<<4) + g;
        af[mt][0] = __float_as_uint(ps[ r0   *68 + ks+tg  ]);
        af[mt][1] = __float_as_uint(ps[(r0+8)*68 + ks+tg  ]);
        af[mt][2] = __float_as_uint(ps[ r0   *68 + ks+tg+4]);
        af[mt][3] = __float_as_uint(ps[(r0+8)*68 + ks+tg+4]);
      }
      #pragma unroll
      for (int nt = 0; nt < 2; nt++){
        int n = wn + (nt<<3) + g;
        bf[nt][0] = __float_as_uint(vs[(ks+tg  )*68 + n]);
        bf[nt][1] = __float_as_uint(vs[(ks+tg+4)*68 + n]);
      }
      #pragma unroll
      for (int mt = 0; mt < 2; mt++)
        #pragma unroll
        for (int nt = 0; nt < 2; nt++)
          mma_tf32(acc[mt][nt], af[mt], bf[nt]);
    }
    __syncthreads();
  }

  float* tvs = sm + PV_TVS;
  for (int f = t; f < 88*68; f += 256) tvs[f] = 0.f;
  __syncthreads();
  for (int f = t; f < NBKT*64; f += 256){
    int c = f >> 6, d = f & 63;
    tvs[c*68 + d] = __uint_as_float(f2tf32(tv[f]));
  }
  if (t < 64){
    float ssum = 0.f;
    #pragma unroll
    for (int c = 0; c < NBKT; c++) ssum += sb[t*88 + c];
    rsv[t] = 1.0f / ssum;
  }
  __syncthreads();

  #pragma unroll
  for (int ks = 0; ks < 88; ks += 8){
    uint32_t af[2][4], bf[2][2];
    #pragma unroll
    for (int mt = 0; mt < 2; mt++){
      int r0 = wm + (mt<<4) + g;
      af[mt][0] = __float_as_uint(sb[ r0   *88 + ks+tg  ]);
      af[mt][1] = __float_as_uint(sb[(r0+8)*88 + ks+tg  ]);
      af[mt][2] = __float_as_uint(sb[ r0   *88 + ks+tg+4]);
      af[mt][3] = __float_as_uint(sb[(r0+8)*88 + ks+tg+4]);
    }
    #pragma unroll
    for (int nt = 0; nt < 2; nt++){
      int n = wn + (nt<<3) + g;
      bf[nt][0] = __float_as_uint(tvs[(ks+tg  )*68 + n]);
      bf[nt][1] = __float_as_uint(tvs[(ks+tg+4)*68 + n]);
    }
    #pragma unroll
    for (int mt = 0; mt < 2; mt++)
      #pragma unroll
      for (int nt = 0; nt < 2; nt++)
        mma_tf32(acc[mt][nt], af[mt], bf[nt]);
  }

  #pragma unroll
  for (int mt = 0; mt < 2; mt++){
    #pragma unroll
    for (int hh = 0; hh < 2; hh++){
      int r = wm + (mt<<4) + g + (hh<<3);
      float inv = rsv[r];
      #pragma unroll
      for (int nt = 0; nt < 2; nt++){
        int col = wn + (nt<<3) + (tg<<1);
        float o0 = acc[mt][nt][hh*2+0] * inv;
        float o1 = acc[mt][nt][hh*2+1] * inv;
        float* op = out + ((size_t)(b<<10) + i0 + r)*CDIM + (h<<6) + col;
        *(float2*)op = make_float2(o0, o1);
      }
    }
  }
}

// ---------------- launch ----------------------------------------------------
extern "C" void kernel_launch(void* const* d_in, const int* in_sizes, int n_in,
                              void* d_out, int out_size)
{
  const float* x0     = (const float*)d_in[0];
  const float* x1     = (const float*)d_in[1];
  const float* ln00_g = (const float*)d_in[2];
  const float* ln00_b = (const float*)d_in[3];
  const float* ln01_g = (const float*)d_in[4];
  const float* ln01_b = (const float*)d_in[5];
  const float* ln10_g = (const float*)d_in[6];
  const float* ln10_b = (const float*)d_in[7];
  const float* ln11_g = (const float*)d_in[8];
  const float* ln11_b = (const float*)d_in[9];
  const float* w_qkv0 = (const float*)d_in[10];
  const float* b_qkv0 = (const float*)d_in[11];
  const float* w_qkv1 = (const float*)d_in[12];
  const float* b_qkv1 = (const float*)d_in[13];
  const float* w_proj = (const float*)d_in[14];
  const float* b_proj = (const float*)d_in[15];
  const float* table_q= (const float*)d_in[16];
  const float* table_k= (const float*)d_in[17];
  const float* table_v= (const float*)d_in[18];
  const float* w_fc1_0= (const float*)d_in[19];
  const float* b_fc1_0= (const float*)d_in[20];
  const float* w_fc2_0= (const float*)d_in[21];
  const float* b_fc2_0= (const float*)d_in[22];
  const float* w_fc1_1= (const float*)d_in[23];
  const float* b_fc1_1= (const float*)d_in[24];
  const float* w_fc2_1= (const float*)d_in[25];
  const float* b_fc2_1= (const float*)d_in[26];

  float* out0 = (float*)d_out;
  float* out1 = (float*)d_out + (size_t)ROWS*CDIM;

  float *ln0, *ln1, *qkv0, *qkv1, *att0, *att1;
  float *lg0, *lg1, *ml0, *ml1, *hid0, *hid1;
  __nv_bfloat16 *lk0, *lk1, *lq0, *lq1;
  cudaGetSymbolAddress((void**)&ln0,  g_ln);     ln1  = ln0  + (size_t)ROWS*CDIM;
  cudaGetSymbolAddress((void**)&qkv0, g_qkv);    qkv1 = qkv0 + (size_t)ROWS*QKVD;
  cudaGetSymbolAddress((void**)&att0, g_att);    att1 = att0 + (size_t)ROWS*CDIM;
  cudaGetSymbolAddress((void**)&lk0,  g_lkb);    lk1  = lk0  + (size_t)BHN*LSTR;
  cudaGetSymbolAddress((void**)&lq0,  g_lqb);    lq1  = lq0  + (size_t)BHN*LSTR;
  cudaGetSymbolAddress((void**)&lg0,  g_logits); lg1  = lg0  + (size_t)32*NQ*NQ;
  cudaGetSymbolAddress((void**)&ml0,  g_ml);     ml1  = ml0  + (size_t)BHN;
  cudaGetSymbolAddress((void**)&hid0, g_hid);    hid1 = hid0 + (size_t)ROWS*HID;

  const int LOGITS_SMEM = LG_SMEM_FLOATS * 4;   // 86272 B
  const int PV_SMEM     = PV_SMEM_FLOATS * 4;
  static int attr_done = 0;
  if (!attr_done){
    cudaFuncSetAttribute(logits_kernel, cudaFuncAttributeMaxDynamicSharedMemorySize, LOGITS_SMEM);
    cudaFuncSetAttribute(pv_kernel,     cudaFuncAttributeMaxDynamicSharedMemorySize, PV_SMEM);
    attr_done = 1;
  }

  // 1. LN (both streams)
  dim3 gln(ROWS, 2);
  ln_kernel<<<gln, 128>>>(x0, x1, ln00_g, ln01_g, ln00_b, ln01_b, ln0, ln1);

  // 2. qkv GEMMs (paired, BN=128)
  {
    GemmPtrs p{{ln0, ln1},{w_qkv0, w_qkv1},{b_qkv0, b_qkv1},{nullptr,nullptr},{qkv0, qkv1}};
    dim3 gg(QKVD/128, ROWS/128, 2);
    sgemm_tf32_kernel<128><<<gg, 256>>>(p, ROWS, QKVD, CDIM, 0);
  }

  // 3. bias tables (bf16, stride 88)
  dim3 gbt(BHN/64, 2, 2);
  biastab_kernel<<<gbt, 256>>>(qkv0, qkv1, table_q, table_k, lk0, lk1, lq0, lq1);

  // 4. strip logits + direct row max
  dim3 glg(16, 64);
  logits_kernel<<<glg, 256, LOGITS_SMEM>>>(qkv0, qkv1, lk0, lk1, lq0, lq1,
                                           lg0, lg1, ml0, ml1);

  // 5. PV + tv table
  dim3 gpv(16, 64);
  pv_kernel<<<gpv, 256, PV_SMEM>>>(lg0, lg1, ml0, ml1, qkv0, qkv1, table_v, att0, att1);

  // 6. proj + residual (paired, BN=64)
  {
    GemmPtrs p{{att0, att1},{w_proj, w_proj},{b_proj, b_proj},{x0, x1},{out0, out1}};
    dim3 gg(CDIM/64, ROWS/128, 2);
    sgemm_tf32_kernel<64><<<gg, 256>>>(p, ROWS, CDIM, CDIM, 0);
  }

  // 7. MLP
  ln_kernel<<<gln, 128>>>(out0, out1, ln10_g, ln11_g, ln10_b, ln11_b, ln0, ln1);

  {
    GemmPtrs p{{ln0, ln1},{w_fc1_0, w_fc1_1},{b_fc1_0, b_fc1_1},{nullptr,nullptr},{hid0, hid1}};
    dim3 gg(HID/128, ROWS/128, 2);
    sgemm_tf32_kernel<128><<<gg, 256>>>(p, ROWS, HID, CDIM, 1);
  }
  {
    GemmPtrs p{{hid0, hid1},{w_fc2_0, w_fc2_1},{b_fc2_0, b_fc2_1},{out0, out1},{out0, out1}};
    dim3 gg(CDIM/64, ROWS/128, 2);
    sgemm_tf32_kernel<64><<<gg, 256>>>(p, ROWS, CDIM, HID, 0);
  }
}